// round 7
// baseline (speedup 1.0000x reference)
#include <cuda_runtime.h>
#include <cuda_bf16.h>
#include <cstdint>
#include <math.h>

// ---------------------------------------------------------------------------
// img_attention, mma.sync (HMMA) split-bf16 path, fused-weight algebra:
//   WfT    = (Wg @ Gs)^T            [1024, 4096]
//   bfused = bg @ Gs + bgs          [1024]
//   g_star = gf @ Wf + bfused       [M, 1024]
//   wgs    = g_star @ Wgs           [M, 1024]
//   dec    = s_t_hat @ Wdec + bdec  [32, 1024]
//   scores = tanh(wgs + dec + cov) @ v; alpha = softmax_T; c = alpha @ g_star
// Output: [c_img (b*DH) | coverage_new (b*T) | alpha (b*T)]
// ---------------------------------------------------------------------------

// ---- scratch (__device__ globals; allocation-free rule) ----
__device__ __align__(1024) __nv_bfloat16 g_gf_hi[25690112];
__device__ __align__(1024) __nv_bfloat16 g_gf_lo[25690112];
__device__ __align__(1024) __nv_bfloat16 g_Wg_hi[16777216];
__device__ __align__(1024) __nv_bfloat16 g_Wg_lo[16777216];
__device__ __align__(1024) __nv_bfloat16 g_GsT_hi[4194304];
__device__ __align__(1024) __nv_bfloat16 g_GsT_lo[4194304];
__device__ __align__(1024) __nv_bfloat16 g_WfT_hi[4194304];
__device__ __align__(1024) __nv_bfloat16 g_WfT_lo[4194304];
__device__ __align__(1024) __nv_bfloat16 g_WgsT_hi[1048576];
__device__ __align__(1024) __nv_bfloat16 g_WgsT_lo[1048576];
__device__ __align__(1024) float g_Gstar[6422528];
__device__ __align__(1024) __nv_bfloat16 g_Gstar_hi[6422528];
__device__ __align__(1024) __nv_bfloat16 g_Gstar_lo[6422528];
__device__ __align__(1024) float g_Wgstar[6422528];
__device__ __align__(1024) float g_bfused[1024];
__device__ __align__(1024) float g_dec[32768];
__device__ __align__(1024) float g_scores[6272];
__device__ __align__(1024) float g_alpha[6272];

// ---------------------------------------------------------------------------
// helpers
// ---------------------------------------------------------------------------
__device__ __forceinline__ uint32_t smem_u32(const void* p) {
    uint32_t a;
    asm("{ .reg .u64 t; cvta.to.shared.u64 t, %1; cvt.u32.u64 %0, t; }" : "=r"(a) : "l"(p));
    return a;
}
__device__ __forceinline__ void cp16(uint32_t s, const void* g) {
    asm volatile("cp.async.cg.shared.global [%0], [%1], 16;" :: "r"(s), "l"(g));
}
__device__ __forceinline__ void ldsm4(uint32_t* r, uint32_t a) {
    asm volatile("ldmatrix.sync.aligned.m8n8.x4.shared.b16 {%0,%1,%2,%3}, [%4];"
                 : "=r"(r[0]), "=r"(r[1]), "=r"(r[2]), "=r"(r[3]) : "r"(a));
}
__device__ __forceinline__ void mma16816(float* d, const uint32_t* a, const uint32_t* b) {
    asm volatile(
        "mma.sync.aligned.m16n8k16.row.col.f32.bf16.bf16.f32 "
        "{%0,%1,%2,%3}, {%4,%5,%6,%7}, {%8,%9}, {%0,%1,%2,%3};"
        : "+f"(d[0]), "+f"(d[1]), "+f"(d[2]), "+f"(d[3])
        : "r"(a[0]), "r"(a[1]), "r"(a[2]), "r"(a[3]), "r"(b[0]), "r"(b[1]));
}
__device__ __forceinline__ uint32_t pack_bf2(float x, float y) {
    __nv_bfloat162 h = __floats2bfloat162_rn(x, y);
    return *(uint32_t*)&h;
}

// MUFU-free tanh (FMA poly exp2 + Newton reciprocal), abs err ~3e-6.
__device__ __forceinline__ float tanh_fma(float x) {
    float ax = fminf(fabsf(x), 9.0f);
    float y  = -2.88539008f * ax;
    float nf = rintf(y);
    float f  = y - nf;
    float p  = 1.33335581e-3f;
    p = fmaf(p, f, 9.61812910e-3f);
    p = fmaf(p, f, 5.55041087e-2f);
    p = fmaf(p, f, 2.40226507e-1f);
    p = fmaf(p, f, 6.93147181e-1f);
    p = fmaf(p, f, 1.0f);
    int ni = (int)nf;
    float u = __int_as_float(__float_as_int(p) + (ni << 23));
    float d = 1.0f + u;
    float r = fmaf(-0.5f, d, 1.45711f);
    r = r * fmaf(-d, r, 2.0f);
    r = r * fmaf(-d, r, 2.0f);
    r = r * fmaf(-d, r, 2.0f);
    return copysignf((1.0f - u) * r, x);
}

// ---------------------------------------------------------------------------
// HMMA GEMM (BN=128): C[M,N] = A[M,K] @ B^T, split-bf16 3xMMA.
// BM=128, BN=128, BK=64, 3-stage cp.async, 8 warps (2m x 4n), warp 64x32.
// ---------------------------------------------------------------------------
#define BKT 64
#define OP_BYTES (128 * 64 * 2)          // 16 KB per operand tile
#define STG_BYTES (4 * OP_BYTES)         // 64 KB per stage
#define GEMM_SMEM (3 * STG_BYTES)        // 192 KB

__device__ __forceinline__ void load_stage(uint32_t stg,
    const __nv_bfloat16* __restrict__ Ah, const __nv_bfloat16* __restrict__ Al,
    const __nv_bfloat16* __restrict__ Bh, const __nv_bfloat16* __restrict__ Bl,
    int brow, int bcol, int K, int k0, int tid)
{
#pragma unroll
    for (int op = 0; op < 4; op++) {
        const __nv_bfloat16* P = (op == 0) ? Ah : (op == 1) ? Al : (op == 2) ? Bh : Bl;
        const int row0 = (op < 2) ? brow : bcol;
#pragma unroll
        for (int it = 0; it < 4; it++) {
            int idx = tid + it * 256;
            int r = idx >> 3, c = idx & 7;
            uint32_t dst = stg + op * OP_BYTES + r * 128 + (((uint32_t)(c ^ (r & 7))) << 4);
            cp16(dst, P + (size_t)(row0 + r) * K + k0 + c * 8);
        }
    }
}

__global__ __launch_bounds__(256, 1)
void tc_gemm(const __nv_bfloat16* __restrict__ Ahi, const __nv_bfloat16* __restrict__ Alo,
             const __nv_bfloat16* __restrict__ Bhi, const __nv_bfloat16* __restrict__ Blo,
             const float* __restrict__ bias,
             float* __restrict__ Cf, __nv_bfloat16* __restrict__ Chi,
             __nv_bfloat16* __restrict__ Clo,
             int M, int N, int K)
{
    extern __shared__ __align__(128) char smem[];
    const uint32_t sbase = smem_u32(smem);
    const int tid = threadIdx.x, wid = tid >> 5, lane = tid & 31;
    const int wm = wid >> 2, wn = wid & 3;
    const int brow = blockIdx.y * 128, bcol = blockIdx.x * 128;
    const int KT = K / BKT;

    const int rowA = wm * 64 + (lane & 15);
    const int phA  = rowA & 7;
    const int hiA  = lane >> 4;
    const int rowB = wn * 32 + ((lane >> 4) << 3) + (lane & 7);
    const int phB  = lane & 7;
    const int hiB  = (lane >> 3) & 1;

    float acc[4][4][4];
#pragma unroll
    for (int mt = 0; mt < 4; mt++)
#pragma unroll
        for (int nt = 0; nt < 4; nt++)
#pragma unroll
            for (int j = 0; j < 4; j++) acc[mt][nt][j] = 0.0f;

    load_stage(sbase, Ahi, Alo, Bhi, Blo, brow, bcol, K, 0, tid);
    asm volatile("cp.async.commit_group;" ::: "memory");
    if (KT > 1) {
        load_stage(sbase + STG_BYTES, Ahi, Alo, Bhi, Blo, brow, bcol, K, BKT, tid);
        asm volatile("cp.async.commit_group;" ::: "memory");
    }

    for (int kt = 0; kt < KT; kt++) {
        // pending here: tiles kt, kt+1. Drain kt before reading it.
        if (kt + 1 < KT) asm volatile("cp.async.wait_group 1;" ::: "memory");
        else             asm volatile("cp.async.wait_group 0;" ::: "memory");
        __syncthreads();

        // issue loads for kt+2 FIRST (buffer (kt+2)%3 freed at iter kt-1),
        // so DMA overlaps the whole compute phase below.
        if (kt + 2 < KT) {
            load_stage(sbase + ((kt + 2) % 3) * STG_BYTES,
                       Ahi, Alo, Bhi, Blo, brow, bcol, K, (kt + 2) * BKT, tid);
            asm volatile("cp.async.commit_group;" ::: "memory");
        }

        const uint32_t stg = sbase + (kt % 3) * STG_BYTES;
        const uint32_t aH = stg, aL = stg + OP_BYTES;
        const uint32_t bH = stg + 2 * OP_BYTES, bL = stg + 3 * OP_BYTES;

#pragma unroll
        for (int ks = 0; ks < 4; ks++) {
            uint32_t ah[4][4], al[4][4], bh[2][4], bl[2][4];
            const uint32_t cA = ((uint32_t)((ks * 2 + hiA) ^ phA)) << 4;
            const uint32_t cB = ((uint32_t)((ks * 2 + hiB) ^ phB)) << 4;
#pragma unroll
            for (int mt = 0; mt < 4; mt++) {
                uint32_t ro = (uint32_t)(rowA + mt * 16) * 128 + cA;
                ldsm4(ah[mt], aH + ro);
                ldsm4(al[mt], aL + ro);
            }
#pragma unroll
            for (int p = 0; p < 2; p++) {
                uint32_t ro = (uint32_t)(rowB + p * 16) * 128 + cB;
                ldsm4(bh[p], bH + ro);
                ldsm4(bl[p], bL + ro);
            }
#pragma unroll
            for (int mt = 0; mt < 4; mt++)
#pragma unroll
                for (int nt = 0; nt < 4; nt++) {
                    float* d = acc[mt][nt];
                    const uint32_t* bhf = &bh[nt >> 1][(nt & 1) * 2];
                    const uint32_t* blf = &bl[nt >> 1][(nt & 1) * 2];
                    mma16816(d, ah[mt], bhf);
                    mma16816(d, ah[mt], blf);
                    mma16816(d, al[mt], bhf);
                }
        }
    }

#pragma unroll
    for (int mt = 0; mt < 4; mt++)
#pragma unroll
        for (int nt = 0; nt < 4; nt++) {
            const int r0 = brow + wm * 64 + mt * 16 + (lane >> 2);
            const int c0 = bcol + wn * 32 + nt * 8 + (lane & 3) * 2;
            float v0 = acc[mt][nt][0], v1 = acc[mt][nt][1];
            float v2 = acc[mt][nt][2], v3 = acc[mt][nt][3];
            if (bias) {
                float b0 = bias[c0], b1 = bias[c0 + 1];
                v0 += b0; v1 += b1; v2 += b0; v3 += b1;
            }
            const size_t o0 = (size_t)r0 * N + c0;
            const size_t o1 = (size_t)(r0 + 8) * N + c0;
            if (Cf) {
                *(float2*)&Cf[o0] = make_float2(v0, v1);
                *(float2*)&Cf[o1] = make_float2(v2, v3);
            }
            if (Chi) {
                __nv_bfloat16 h0 = __float2bfloat16(v0), h1 = __float2bfloat16(v1);
                __nv_bfloat16 h2 = __float2bfloat16(v2), h3 = __float2bfloat16(v3);
                *(uint32_t*)&Chi[o0] = pack_bf2(__bfloat162float(h0), __bfloat162float(h1));
                *(uint32_t*)&Chi[o1] = pack_bf2(__bfloat162float(h2), __bfloat162float(h3));
                *(uint32_t*)&Clo[o0] = pack_bf2(v0 - __bfloat162float(h0), v1 - __bfloat162float(h1));
                *(uint32_t*)&Clo[o1] = pack_bf2(v2 - __bfloat162float(h2), v3 - __bfloat162float(h3));
            }
        }
}

// ---------------------------------------------------------------------------
// HMMA GEMM (BN=256, 2-stage): for the WfT precompute (one full wave, higher
// arithmetic intensity). Warp tile 64x64, split-bf16 3xMMA, bf16 hi/lo output.
// ---------------------------------------------------------------------------
#define OPA2 (128 * 64 * 2)              // 16 KB
#define OPB2 (256 * 64 * 2)              // 32 KB
#define STG2 (2 * OPA2 + 2 * OPB2)       // 96 KB per stage; 2 stages = 192 KB

__device__ __forceinline__ void load_stage_n256(uint32_t stg,
    const __nv_bfloat16* __restrict__ Ah, const __nv_bfloat16* __restrict__ Al,
    const __nv_bfloat16* __restrict__ Bh, const __nv_bfloat16* __restrict__ Bl,
    int brow, int bcol, int K, int k0, int tid)
{
#pragma unroll
    for (int op = 0; op < 2; op++) {
        const __nv_bfloat16* P = op ? Al : Ah;
#pragma unroll
        for (int it = 0; it < 4; it++) {
            int idx = tid + it * 256;
            int r = idx >> 3, c = idx & 7;
            uint32_t dst = stg + op * OPA2 + r * 128 + (((uint32_t)(c ^ (r & 7))) << 4);
            cp16(dst, P + (size_t)(brow + r) * K + k0 + c * 8);
        }
    }
#pragma unroll
    for (int op = 0; op < 2; op++) {
        const __nv_bfloat16* P = op ? Bl : Bh;
#pragma unroll
        for (int it = 0; it < 8; it++) {
            int idx = tid + it * 256;
            int r = idx >> 3, c = idx & 7;
            uint32_t dst = stg + 2 * OPA2 + op * OPB2 + r * 128
                         + (((uint32_t)(c ^ (r & 7))) << 4);
            cp16(dst, P + (size_t)(bcol + r) * K + k0 + c * 8);
        }
    }
}

__global__ __launch_bounds__(256, 1)
void tc_gemm_n256(const __nv_bfloat16* __restrict__ Ahi, const __nv_bfloat16* __restrict__ Alo,
                  const __nv_bfloat16* __restrict__ Bhi, const __nv_bfloat16* __restrict__ Blo,
                  __nv_bfloat16* __restrict__ Chi, __nv_bfloat16* __restrict__ Clo,
                  int M, int N, int K)
{
    extern __shared__ __align__(128) char smem[];
    const uint32_t sbase = smem_u32(smem);
    const int tid = threadIdx.x, wid = tid >> 5, lane = tid & 31;
    const int wm = wid >> 2, wn = wid & 3;          // 2m x 4n; warp tile 64x64
    const int brow = blockIdx.y * 128, bcol = blockIdx.x * 256;
    const int KT = K / BKT;

    const int rowA = wm * 64 + (lane & 15);
    const int phA  = rowA & 7;
    const int hiA  = lane >> 4;
    const int rowBb = wn * 64 + ((lane >> 4) << 3) + (lane & 7);
    const int phB  = lane & 7;
    const int hiB  = (lane >> 3) & 1;

    float acc[4][8][4];
#pragma unroll
    for (int mt = 0; mt < 4; mt++)
#pragma unroll
        for (int nt = 0; nt < 8; nt++)
#pragma unroll
            for (int j = 0; j < 4; j++) acc[mt][nt][j] = 0.0f;

    load_stage_n256(sbase, Ahi, Alo, Bhi, Blo, brow, bcol, K, 0, tid);
    asm volatile("cp.async.commit_group;" ::: "memory");

    for (int kt = 0; kt < KT; kt++) {
        asm volatile("cp.async.wait_group 0;" ::: "memory");
        __syncthreads();

        // prefetch kt+1 into the other stage; overlaps compute below.
        if (kt + 1 < KT) {
            load_stage_n256(sbase + ((kt + 1) & 1) * STG2,
                            Ahi, Alo, Bhi, Blo, brow, bcol, K, (kt + 1) * BKT, tid);
            asm volatile("cp.async.commit_group;" ::: "memory");
        }

        const uint32_t stg = sbase + (kt & 1) * STG2;
        const uint32_t aH = stg, aL = stg + OPA2;
        const uint32_t bH = stg + 2 * OPA2, bL = stg + 2 * OPA2 + OPB2;

#pragma unroll
        for (int ks = 0; ks < 4; ks++) {
            const uint32_t cA = ((uint32_t)((ks * 2 + hiA) ^ phA)) << 4;
            const uint32_t cB = ((uint32_t)((ks * 2 + hiB) ^ phB)) << 4;
            uint32_t ah[4][4], al[4][4];
#pragma unroll
            for (int mt = 0; mt < 4; mt++) {
                uint32_t ro = (uint32_t)(rowA + mt * 16) * 128 + cA;
                ldsm4(ah[mt], aH + ro);
                ldsm4(al[mt], aL + ro);
            }
#pragma unroll
            for (int half = 0; half < 2; half++) {
                uint32_t bh[2][4], bl[2][4];
#pragma unroll
                for (int p = 0; p < 2; p++) {
                    uint32_t ro = (uint32_t)(rowBb + half * 32 + p * 16) * 128 + cB;
                    ldsm4(bh[p], bH + ro);
                    ldsm4(bl[p], bL + ro);
                }
#pragma unroll
                for (int mt = 0; mt < 4; mt++)
#pragma unroll
                    for (int ntl = 0; ntl < 4; ntl++) {
                        float* d = acc[mt][half * 4 + ntl];
                        const uint32_t* bhf = &bh[ntl >> 1][(ntl & 1) * 2];
                        const uint32_t* blf = &bl[ntl >> 1][(ntl & 1) * 2];
                        mma16816(d, ah[mt], bhf);
                        mma16816(d, ah[mt], blf);
                        mma16816(d, al[mt], bhf);
                    }
            }
        }
    }

#pragma unroll
    for (int mt = 0; mt < 4; mt++)
#pragma unroll
        for (int nt = 0; nt < 8; nt++) {
            const int r0 = brow + wm * 64 + mt * 16 + (lane >> 2);
            const int c0 = bcol + wn * 64 + nt * 8 + (lane & 3) * 2;
            float v0 = acc[mt][nt][0], v1 = acc[mt][nt][1];
            float v2 = acc[mt][nt][2], v3 = acc[mt][nt][3];
            const size_t o0 = (size_t)r0 * N + c0;
            const size_t o1 = (size_t)(r0 + 8) * N + c0;
            __nv_bfloat16 h0 = __float2bfloat16(v0), h1 = __float2bfloat16(v1);
            __nv_bfloat16 h2 = __float2bfloat16(v2), h3 = __float2bfloat16(v3);
            *(uint32_t*)&Chi[o0] = pack_bf2(__bfloat162float(h0), __bfloat162float(h1));
            *(uint32_t*)&Chi[o1] = pack_bf2(__bfloat162float(h2), __bfloat162float(h3));
            *(uint32_t*)&Clo[o0] = pack_bf2(v0 - __bfloat162float(h0), v1 - __bfloat162float(h1));
            *(uint32_t*)&Clo[o1] = pack_bf2(v2 - __bfloat162float(h2), v3 - __bfloat162float(h3));
        }
}

// ---------------------------------------------------------------------------
// conversion kernels
// ---------------------------------------------------------------------------
__global__ void split_f32(const float* __restrict__ in, __nv_bfloat16* __restrict__ hi,
                          __nv_bfloat16* __restrict__ lo, int n4)
{
    int i = blockIdx.x * blockDim.x + threadIdx.x;
    if (i >= n4) return;
    float4 v = ((const float4*)in)[i];
    __nv_bfloat16 h0 = __float2bfloat16(v.x), h1 = __float2bfloat16(v.y);
    __nv_bfloat16 h2 = __float2bfloat16(v.z), h3 = __float2bfloat16(v.w);
    ((uint2*)hi)[i] = make_uint2(pack_bf2(__bfloat162float(h0), __bfloat162float(h1)),
                                 pack_bf2(__bfloat162float(h2), __bfloat162float(h3)));
    ((uint2*)lo)[i] = make_uint2(pack_bf2(v.x - __bfloat162float(h0), v.y - __bfloat162float(h1)),
                                 pack_bf2(v.z - __bfloat162float(h2), v.w - __bfloat162float(h3)));
}

__global__ void transpose_split(const float* __restrict__ in,
                                __nv_bfloat16* __restrict__ hi,
                                __nv_bfloat16* __restrict__ lo, int K, int N)
{
    __shared__ float t[32][33];
    const int n0 = blockIdx.x * 32, k0 = blockIdx.y * 32;
    const int tx = threadIdx.x, ty = threadIdx.y;
#pragma unroll
    for (int i = 0; i < 32; i += 8)
        t[ty + i][tx] = in[(size_t)(k0 + ty + i) * N + n0 + tx];
    __syncthreads();
#pragma unroll
    for (int i = 0; i < 32; i += 8) {
        float v = t[tx][ty + i];
        __nv_bfloat16 h = __float2bfloat16(v);
        const size_t o = (size_t)(n0 + ty + i) * K + k0 + tx;
        hi[o] = h;
        lo[o] = __float2bfloat16(v - __bfloat162float(h));
    }
}

// bfused[n] = sum_k bg[k] * Gs[k,n] + bgs[n]
__global__ void bfused_kernel(const float* __restrict__ bg, const float* __restrict__ Gs,
                              const float* __restrict__ bgs, float* __restrict__ out,
                              int K, int N)
{
    __shared__ float red[8][32];
    const int c  = threadIdx.x & 31;
    const int kg = threadIdx.x >> 5;
    const int n  = blockIdx.x * 32 + c;
    const int kslice = K / 8;
    float acc = 0.0f;
    const float* p = Gs + (size_t)(kg * kslice) * N + n;
#pragma unroll 8
    for (int k = 0; k < kslice; k++)
        acc = fmaf(bg[kg * kslice + k], p[(size_t)k * N], acc);
    red[kg][c] = acc;
    __syncthreads();
    if (kg == 0) {
        float s = bgs[n];
#pragma unroll
        for (int i = 0; i < 8; i++) s += red[i][c];
        out[n] = s;
    }
}

__global__ void dec_proj(const float* __restrict__ sth, const float* __restrict__ W,
                         const float* __restrict__ bias, float* __restrict__ out)
{
    __shared__ float s[1024];
    const int b = blockIdx.y;
    const int col = blockIdx.x * 128 + threadIdx.x;
    for (int k = threadIdx.x; k < 1024; k += 128) s[k] = sth[b * 1024 + k];
    __syncthreads();
    float acc = 0.0f;
#pragma unroll 16
    for (int k = 0; k < 1024; k++) acc = fmaf(s[k], W[(size_t)k * 1024 + col], acc);
    out[b * 1024 + col] = acc + bias[col];
}

// ---------------------------------------------------------------------------
// attention tail
// ---------------------------------------------------------------------------
__global__ void scores_kernel(const float* __restrict__ Wgstar,
                              const float* __restrict__ dec,
                              const float* __restrict__ cov,
                              const float* __restrict__ v,
                              float* __restrict__ scores, int T, int DH)
{
    const int bt = blockIdx.x;
    const int b = bt / T;
    const float c = cov[bt];
    const float4* w4 = (const float4*)(Wgstar + (size_t)bt * DH);
    const float4* d4 = (const float4*)(dec + (size_t)b * DH);
    const float4* v4 = (const float4*)v;

    float s = 0.0f;
    for (int i = threadIdx.x; i < DH / 4; i += 256) {
        float4 w = w4[i], dd = d4[i], vv = v4[i];
        s += tanh_fma(w.x + dd.x + c) * vv.x;
        s += tanh_fma(w.y + dd.y + c) * vv.y;
        s += tanh_fma(w.z + dd.z + c) * vv.z;
        s += tanh_fma(w.w + dd.w + c) * vv.w;
    }
#pragma unroll
    for (int o = 16; o > 0; o >>= 1) s += __shfl_xor_sync(0xffffffffu, s, o);
    __shared__ float red[8];
    if ((threadIdx.x & 31) == 0) red[threadIdx.x >> 5] = s;
    __syncthreads();
    if (threadIdx.x == 0) {
        float t = 0.0f;
#pragma unroll
        for (int i = 0; i < 8; i++) t += red[i];
        scores[bt] = t;
    }
}

__global__ void softmax_kernel(const float* __restrict__ scores,
                               const float* __restrict__ cov,
                               float* __restrict__ alpha,
                               float* __restrict__ out_cov,
                               float* __restrict__ out_alpha, int T)
{
    const int b = blockIdx.x;
    const int tid = threadIdx.x;
    __shared__ float red[256];
    float m = -1e30f;
    for (int t = tid; t < T; t += blockDim.x) m = fmaxf(m, scores[b * T + t]);
    red[tid] = m;
    __syncthreads();
    for (int off = 128; off > 0; off >>= 1) {
        if (tid < off) red[tid] = fmaxf(red[tid], red[tid + off]);
        __syncthreads();
    }
    m = red[0];
    __syncthreads();
    float s = 0.0f;
    for (int t = tid; t < T; t += blockDim.x) s += expf(scores[b * T + t] - m);
    red[tid] = s;
    __syncthreads();
    for (int off = 128; off > 0; off >>= 1) {
        if (tid < off) red[tid] += red[tid + off];
        __syncthreads();
    }
    s = red[0];
    const float inv = 1.0f / s;
    for (int t = tid; t < T; t += blockDim.x) {
        float a = expf(scores[b * T + t] - m) * inv;
        alpha[b * T + t] = a;
        out_alpha[b * T + t] = a;
        out_cov[b * T + t] = cov[b * T + t] + a;
    }
}

__global__ void context_kernel(const float* __restrict__ alpha,
                               const float* __restrict__ Gstar,
                               float* __restrict__ out_c, int T, int DH)
{
    const int b = blockIdx.x;
    const int d = blockIdx.y * 128 + threadIdx.x;
    __shared__ float a_s[256];
    for (int t = threadIdx.x; t < T; t += blockDim.x) a_s[t] = alpha[b * T + t];
    __syncthreads();
    const float* gbase = Gstar + (size_t)b * T * DH + d;
    float acc = 0.0f;
#pragma unroll 4
    for (int t = 0; t < T; t++)
        acc = fmaf(a_s[t], gbase[(size_t)t * DH], acc);
    out_c[(size_t)b * DH + d] = acc;
}

// ---------------------------------------------------------------------------
extern "C" void kernel_launch(void* const* d_in, const int* in_sizes, int n_in,
                              void* d_out, int out_size)
{
    const float* gf   = (const float*)d_in[0];
    const float* sth  = (const float*)d_in[1];
    const float* cov  = (const float*)d_in[2];
    const float* Wg   = (const float*)d_in[3];
    const float* bg   = (const float*)d_in[4];
    const float* Gs   = (const float*)d_in[5];
    const float* bgs  = (const float*)d_in[6];
    const float* Wgs  = (const float*)d_in[7];
    const float* Wdec = (const float*)d_in[8];
    const float* bdec = (const float*)d_in[9];
    const float* v    = (const float*)d_in[10];

    const int GFD = in_sizes[4];        // 4096
    const int DH  = in_sizes[9];        // 1024
    const int b   = in_sizes[1] / DH;   // 32
    const int T   = in_sizes[2] / b;    // 196
    const int M   = b * T;              // 6272

    __nv_bfloat16 *gf_hi, *gf_lo, *Wg_hi, *Wg_lo, *GsT_hi, *GsT_lo;
    __nv_bfloat16 *WfT_hi, *WfT_lo, *WgsT_hi, *WgsT_lo, *Gstar_hi, *Gstar_lo;
    float *Gstar, *Wgstar, *bfused, *dec, *scores, *alpha;
    cudaGetSymbolAddress((void**)&gf_hi, g_gf_hi);
    cudaGetSymbolAddress((void**)&gf_lo, g_gf_lo);
    cudaGetSymbolAddress((void**)&Wg_hi, g_Wg_hi);
    cudaGetSymbolAddress((void**)&Wg_lo, g_Wg_lo);
    cudaGetSymbolAddress((void**)&GsT_hi, g_GsT_hi);
    cudaGetSymbolAddress((void**)&GsT_lo, g_GsT_lo);
    cudaGetSymbolAddress((void**)&WfT_hi, g_WfT_hi);
    cudaGetSymbolAddress((void**)&WfT_lo, g_WfT_lo);
    cudaGetSymbolAddress((void**)&WgsT_hi, g_WgsT_hi);
    cudaGetSymbolAddress((void**)&WgsT_lo, g_WgsT_lo);
    cudaGetSymbolAddress((void**)&Gstar, g_Gstar);
    cudaGetSymbolAddress((void**)&Gstar_hi, g_Gstar_hi);
    cudaGetSymbolAddress((void**)&Gstar_lo, g_Gstar_lo);
    cudaGetSymbolAddress((void**)&Wgstar, g_Wgstar);
    cudaGetSymbolAddress((void**)&bfused, g_bfused);
    cudaGetSymbolAddress((void**)&dec, g_dec);
    cudaGetSymbolAddress((void**)&scores, g_scores);
    cudaGetSymbolAddress((void**)&alpha, g_alpha);

    cudaFuncSetAttribute(tc_gemm, cudaFuncAttributeMaxDynamicSharedMemorySize, GEMM_SMEM);
    cudaFuncSetAttribute(tc_gemm_n256, cudaFuncAttributeMaxDynamicSharedMemorySize, 2 * STG2);

    // operand prep
    split_f32<<<(M * GFD / 4 + 255) / 256, 256>>>(gf, gf_hi, gf_lo, M * GFD / 4);
    split_f32<<<(GFD * GFD / 4 + 255) / 256, 256>>>(Wg, Wg_hi, Wg_lo, GFD * GFD / 4);
    transpose_split<<<dim3(DH / 32, GFD / 32), dim3(32, 8)>>>(Gs, GsT_hi, GsT_lo, GFD, DH);
    transpose_split<<<dim3(DH / 32, DH / 32), dim3(32, 8)>>>(Wgs, WgsT_hi, WgsT_lo, DH, DH);
    bfused_kernel<<<DH / 32, 256>>>(bg, Gs, bgs, bfused, GFD, DH);

    // WfT[n,m] = sum_k Gs[k,n] * Wg[m,k]  — BN=256 kernel, one full wave
    tc_gemm_n256<<<dim3(GFD / 256, DH / 128), 256, 2 * STG2>>>(
        GsT_hi, GsT_lo, Wg_hi, Wg_lo, WfT_hi, WfT_lo, DH, GFD, GFD);
    // g_star = gf @ Wf + bfused
    tc_gemm<<<dim3(DH / 128, M / 128), 256, GEMM_SMEM>>>(
        gf_hi, gf_lo, WfT_hi, WfT_lo, bfused, Gstar, Gstar_hi, Gstar_lo, M, DH, GFD);
    // wgs = g_star @ Wgs
    tc_gemm<<<dim3(DH / 128, M / 128), 256, GEMM_SMEM>>>(
        Gstar_hi, Gstar_lo, WgsT_hi, WgsT_lo, nullptr, Wgstar, nullptr, nullptr, M, DH, DH);

    dec_proj<<<dim3(DH / 128, b), 128>>>(sth, Wdec, bdec, dec);
    scores_kernel<<<M, 256>>>(Wgstar, dec, cov, v, scores, T, DH);

    float* out_c     = (float*)d_out;
    float* out_cov   = out_c + (size_t)b * DH;
    float* out_alpha = out_cov + (size_t)b * T;
    softmax_kernel<<<b, 256>>>(scores, cov, alpha, out_cov, out_alpha, T);
    context_kernel<<<dim3(b, DH / 128), 128>>>(alpha, Gstar, out_c, T, DH);
}

// round 8
// speedup vs baseline: 1.0350x; 1.0350x over previous
#include <cuda_runtime.h>
#include <cuda_bf16.h>
#include <cstdint>
#include <math.h>

// ---------------------------------------------------------------------------
// img_attention, mma.sync (HMMA) split-bf16 path, fused-weight algebra:
//   WfT    = (Wg @ Gs)^T            [1024, 4096]
//   bfused = bg @ Gs + bgs          [1024]
//   g_star = gf @ Wf + bfused       [M, 1024]
//   wgs    = g_star @ Wgs  (fused into scores partials, never materialized)
//   dec    = s_t_hat @ Wdec + bdec  [32, 1024]
//   scores = tanh(wgs + dec + cov) @ v; alpha = softmax_T; c = alpha @ g_star
// Output: [c_img (b*DH) | coverage_new (b*T) | alpha (b*T)]
// ---------------------------------------------------------------------------

// ---- scratch (__device__ globals; allocation-free rule) ----
__device__ __align__(1024) __nv_bfloat16 g_gf_hi[25690112];
__device__ __align__(1024) __nv_bfloat16 g_gf_lo[25690112];
__device__ __align__(1024) __nv_bfloat16 g_Wg_hi[16777216];
__device__ __align__(1024) __nv_bfloat16 g_Wg_lo[16777216];
__device__ __align__(1024) __nv_bfloat16 g_GsT_hi[4194304];
__device__ __align__(1024) __nv_bfloat16 g_GsT_lo[4194304];
__device__ __align__(1024) __nv_bfloat16 g_WfT_hi[4194304];
__device__ __align__(1024) __nv_bfloat16 g_WfT_lo[4194304];
__device__ __align__(1024) __nv_bfloat16 g_WgsT_hi[1048576];
__device__ __align__(1024) __nv_bfloat16 g_WgsT_lo[1048576];
__device__ __align__(1024) float g_Gstar[6422528];
__device__ __align__(1024) __nv_bfloat16 g_Gstar_hi[6422528];
__device__ __align__(1024) __nv_bfloat16 g_Gstar_lo[6422528];
__device__ __align__(1024) float g_bfused[1024];
__device__ __align__(1024) float g_dec[32768];
__device__ __align__(1024) float g_scores_part[50176];   // [M][8]
__device__ __align__(1024) float g_alpha[6272];

// ---------------------------------------------------------------------------
// helpers
// ---------------------------------------------------------------------------
__device__ __forceinline__ uint32_t smem_u32(const void* p) {
    uint32_t a;
    asm("{ .reg .u64 t; cvta.to.shared.u64 t, %1; cvt.u32.u64 %0, t; }" : "=r"(a) : "l"(p));
    return a;
}
__device__ __forceinline__ void cp16(uint32_t s, const void* g) {
    asm volatile("cp.async.cg.shared.global [%0], [%1], 16;" :: "r"(s), "l"(g));
}
__device__ __forceinline__ void ldsm4(uint32_t* r, uint32_t a) {
    asm volatile("ldmatrix.sync.aligned.m8n8.x4.shared.b16 {%0,%1,%2,%3}, [%4];"
                 : "=r"(r[0]), "=r"(r[1]), "=r"(r[2]), "=r"(r[3]) : "r"(a));
}
__device__ __forceinline__ void mma16816(float* d, const uint32_t* a, const uint32_t* b) {
    asm volatile(
        "mma.sync.aligned.m16n8k16.row.col.f32.bf16.bf16.f32 "
        "{%0,%1,%2,%3}, {%4,%5,%6,%7}, {%8,%9}, {%0,%1,%2,%3};"
        : "+f"(d[0]), "+f"(d[1]), "+f"(d[2]), "+f"(d[3])
        : "r"(a[0]), "r"(a[1]), "r"(a[2]), "r"(a[3]), "r"(b[0]), "r"(b[1]));
}
__device__ __forceinline__ uint32_t pack_bf2(float x, float y) {
    __nv_bfloat162 h = __floats2bfloat162_rn(x, y);
    return *(uint32_t*)&h;
}

// MUFU-free tanh (FMA poly exp2 + Newton reciprocal), abs err ~3e-6.
__device__ __forceinline__ float tanh_fma(float x) {
    float ax = fminf(fabsf(x), 9.0f);
    float y  = -2.88539008f * ax;
    float nf = rintf(y);
    float f  = y - nf;
    float p  = 1.33335581e-3f;
    p = fmaf(p, f, 9.61812910e-3f);
    p = fmaf(p, f, 5.55041087e-2f);
    p = fmaf(p, f, 2.40226507e-1f);
    p = fmaf(p, f, 6.93147181e-1f);
    p = fmaf(p, f, 1.0f);
    int ni = (int)nf;
    float u = __int_as_float(__float_as_int(p) + (ni << 23));
    float d = 1.0f + u;
    float r = fmaf(-0.5f, d, 1.45711f);
    r = r * fmaf(-d, r, 2.0f);
    r = r * fmaf(-d, r, 2.0f);
    r = r * fmaf(-d, r, 2.0f);
    return copysignf((1.0f - u) * r, x);
}

// ---------------------------------------------------------------------------
// HMMA GEMM (BN=128): C[M,N] = A[M,K] @ B^T, split-bf16 3xMMA.
// BM=128, BN=128, BK=64, 3-stage cp.async, 8 warps (2m x 4n), warp 64x32.
// (R6-calibrated configuration: loads for kt+2 issued AFTER compute of kt.)
// ---------------------------------------------------------------------------
#define BKT 64
#define OP_BYTES (128 * 64 * 2)          // 16 KB per operand tile
#define STG_BYTES (4 * OP_BYTES)         // 64 KB per stage
#define GEMM_SMEM (3 * STG_BYTES)        // 192 KB

__device__ __forceinline__ void load_stage(uint32_t stg,
    const __nv_bfloat16* __restrict__ Ah, const __nv_bfloat16* __restrict__ Al,
    const __nv_bfloat16* __restrict__ Bh, const __nv_bfloat16* __restrict__ Bl,
    int brow, int bcol, int K, int k0, int tid)
{
#pragma unroll
    for (int op = 0; op < 4; op++) {
        const __nv_bfloat16* P = (op == 0) ? Ah : (op == 1) ? Al : (op == 2) ? Bh : Bl;
        const int row0 = (op < 2) ? brow : bcol;
#pragma unroll
        for (int it = 0; it < 4; it++) {
            int idx = tid + it * 256;
            int r = idx >> 3, c = idx & 7;
            uint32_t dst = stg + op * OP_BYTES + r * 128 + (((uint32_t)(c ^ (r & 7))) << 4);
            cp16(dst, P + (size_t)(row0 + r) * K + k0 + c * 8);
        }
    }
}

// Shared mainloop: leaves acc[][][] with final fp32 results.
#define GEMM_MAINLOOP()                                                        \
    load_stage(sbase, Ahi, Alo, Bhi, Blo, brow, bcol, K, 0, tid);              \
    asm volatile("cp.async.commit_group;" ::: "memory");                       \
    if (KT > 1) {                                                              \
        load_stage(sbase + STG_BYTES, Ahi, Alo, Bhi, Blo, brow, bcol, K, BKT, tid); \
        asm volatile("cp.async.commit_group;" ::: "memory");                   \
    }                                                                          \
    for (int kt = 0; kt < KT; kt++) {                                          \
        if (kt + 1 < KT) asm volatile("cp.async.wait_group 1;" ::: "memory");  \
        else             asm volatile("cp.async.wait_group 0;" ::: "memory");  \
        __syncthreads();                                                       \
        const uint32_t stg = sbase + (kt % 3) * STG_BYTES;                     \
        const uint32_t aH = stg, aL = stg + OP_BYTES;                          \
        const uint32_t bH = stg + 2 * OP_BYTES, bL = stg + 3 * OP_BYTES;       \
        _Pragma("unroll")                                                      \
        for (int ks = 0; ks < 4; ks++) {                                       \
            uint32_t ah[4][4], al[4][4], bh[2][4], bl[2][4];                   \
            const uint32_t cA = ((uint32_t)((ks * 2 + hiA) ^ phA)) << 4;       \
            const uint32_t cB = ((uint32_t)((ks * 2 + hiB) ^ phB)) << 4;       \
            _Pragma("unroll")                                                  \
            for (int mt = 0; mt < 4; mt++) {                                   \
                uint32_t ro = (uint32_t)(rowA + mt * 16) * 128 + cA;           \
                ldsm4(ah[mt], aH + ro);                                        \
                ldsm4(al[mt], aL + ro);                                        \
            }                                                                  \
            _Pragma("unroll")                                                  \
            for (int p = 0; p < 2; p++) {                                      \
                uint32_t ro = (uint32_t)(rowB + p * 16) * 128 + cB;            \
                ldsm4(bh[p], bH + ro);                                         \
                ldsm4(bl[p], bL + ro);                                         \
            }                                                                  \
            _Pragma("unroll")                                                  \
            for (int mt = 0; mt < 4; mt++)                                     \
                _Pragma("unroll")                                              \
                for (int nt = 0; nt < 4; nt++) {                               \
                    float* d = acc[mt][nt];                                    \
                    const uint32_t* bhf = &bh[nt >> 1][(nt & 1) * 2];          \
                    const uint32_t* blf = &bl[nt >> 1][(nt & 1) * 2];          \
                    mma16816(d, ah[mt], bhf);                                  \
                    mma16816(d, ah[mt], blf);                                  \
                    mma16816(d, al[mt], bhf);                                  \
                }                                                              \
        }                                                                      \
        if (kt + 2 < KT) {                                                     \
            load_stage(sbase + ((kt + 2) % 3) * STG_BYTES,                     \
                       Ahi, Alo, Bhi, Blo, brow, bcol, K, (kt + 2) * BKT, tid);\
            asm volatile("cp.async.commit_group;" ::: "memory");               \
        }                                                                      \
    }

#define GEMM_PREAMBLE()                                                        \
    extern __shared__ __align__(128) char smem[];                              \
    const uint32_t sbase = smem_u32(smem);                                     \
    const int tid = threadIdx.x, wid = tid >> 5, lane = tid & 31;              \
    const int wm = wid >> 2, wn = wid & 3;                                     \
    const int brow = blockIdx.y * 128, bcol = blockIdx.x * 128;                \
    const int KT = K / BKT;                                                    \
    const int rowA = wm * 64 + (lane & 15);                                    \
    const int phA  = rowA & 7;                                                 \
    const int hiA  = lane >> 4;                                                \
    const int rowB = wn * 32 + ((lane >> 4) << 3) + (lane & 7);                \
    const int phB  = lane & 7;                                                 \
    const int hiB  = (lane >> 3) & 1;                                          \
    float acc[4][4][4];                                                        \
    _Pragma("unroll")                                                          \
    for (int mt = 0; mt < 4; mt++)                                             \
        _Pragma("unroll")                                                      \
        for (int nt = 0; nt < 4; nt++)                                         \
            _Pragma("unroll")                                                  \
            for (int j = 0; j < 4; j++) acc[mt][nt][j] = 0.0f;

__global__ __launch_bounds__(256, 1)
void tc_gemm(const __nv_bfloat16* __restrict__ Ahi, const __nv_bfloat16* __restrict__ Alo,
             const __nv_bfloat16* __restrict__ Bhi, const __nv_bfloat16* __restrict__ Blo,
             const float* __restrict__ bias,
             float* __restrict__ Cf, __nv_bfloat16* __restrict__ Chi,
             __nv_bfloat16* __restrict__ Clo,
             int M, int N, int K)
{
    GEMM_PREAMBLE();
    GEMM_MAINLOOP();

#pragma unroll
    for (int mt = 0; mt < 4; mt++)
#pragma unroll
        for (int nt = 0; nt < 4; nt++) {
            const int r0 = brow + wm * 64 + mt * 16 + (lane >> 2);
            const int c0 = bcol + wn * 32 + nt * 8 + (lane & 3) * 2;
            float v0 = acc[mt][nt][0], v1 = acc[mt][nt][1];
            float v2 = acc[mt][nt][2], v3 = acc[mt][nt][3];
            if (bias) {
                float b0 = bias[c0], b1 = bias[c0 + 1];
                v0 += b0; v1 += b1; v2 += b0; v3 += b1;
            }
            const size_t o0 = (size_t)r0 * N + c0;
            const size_t o1 = (size_t)(r0 + 8) * N + c0;
            if (Cf) {
                *(float2*)&Cf[o0] = make_float2(v0, v1);
                *(float2*)&Cf[o1] = make_float2(v2, v3);
            }
            if (Chi) {
                __nv_bfloat16 h0 = __float2bfloat16(v0), h1 = __float2bfloat16(v1);
                __nv_bfloat16 h2 = __float2bfloat16(v2), h3 = __float2bfloat16(v3);
                *(uint32_t*)&Chi[o0] = pack_bf2(__bfloat162float(h0), __bfloat162float(h1));
                *(uint32_t*)&Chi[o1] = pack_bf2(__bfloat162float(h2), __bfloat162float(h3));
                *(uint32_t*)&Clo[o0] = pack_bf2(v0 - __bfloat162float(h0), v1 - __bfloat162float(h1));
                *(uint32_t*)&Clo[o1] = pack_bf2(v2 - __bfloat162float(h2), v3 - __bfloat162float(h3));
            }
        }
}

// ---------------------------------------------------------------------------
// GEMM3 fused: wgs tile -> tanh(wgs + dec + cov) * v, reduced over this CTA's
// 128 columns -> scores_part[row][blockIdx.x]. Nothing else written.
// ---------------------------------------------------------------------------
__global__ __launch_bounds__(256, 1)
void tc_gemm_scores(const __nv_bfloat16* __restrict__ Ahi, const __nv_bfloat16* __restrict__ Alo,
                    const __nv_bfloat16* __restrict__ Bhi, const __nv_bfloat16* __restrict__ Blo,
                    const float* __restrict__ dec, const float* __restrict__ cov,
                    const float* __restrict__ vvec, float* __restrict__ scores_part,
                    int M, int N, int K, int T)
{
    GEMM_PREAMBLE();
    GEMM_MAINLOOP();

    __syncthreads();                    // smem stages now reusable as scratch
    float* red = (float*)smem;          // [128][4]

#pragma unroll
    for (int mt = 0; mt < 4; mt++) {
        const int rl0 = wm * 64 + mt * 16 + (lane >> 2);
        const int rl1 = rl0 + 8;
        const int gr0 = brow + rl0, gr1 = brow + rl1;
        const float cov0 = cov[gr0], cov1 = cov[gr1];
        const float* dec0 = dec + (size_t)(gr0 / T) * 1024;
        const float* dec1 = dec + (size_t)(gr1 / T) * 1024;
        float s0 = 0.0f, s1 = 0.0f;
#pragma unroll
        for (int nt = 0; nt < 4; nt++) {
            const int c0 = bcol + wn * 32 + nt * 8 + (lane & 3) * 2;
            const float va = vvec[c0], vb = vvec[c0 + 1];
            const float da = dec0[c0], db = dec0[c0 + 1];
            const float ea = dec1[c0], eb = dec1[c0 + 1];
            s0 += tanh_fma(acc[mt][nt][0] + da + cov0) * va
                + tanh_fma(acc[mt][nt][1] + db + cov0) * vb;
            s1 += tanh_fma(acc[mt][nt][2] + ea + cov1) * va
                + tanh_fma(acc[mt][nt][3] + eb + cov1) * vb;
        }
        s0 += __shfl_xor_sync(0xffffffffu, s0, 1);
        s0 += __shfl_xor_sync(0xffffffffu, s0, 2);
        s1 += __shfl_xor_sync(0xffffffffu, s1, 1);
        s1 += __shfl_xor_sync(0xffffffffu, s1, 2);
        if ((lane & 3) == 0) {
            red[rl0 * 4 + wn] = s0;
            red[rl1 * 4 + wn] = s1;
        }
    }
    __syncthreads();
    if (tid < 128) {
        float t = red[tid * 4] + red[tid * 4 + 1] + red[tid * 4 + 2] + red[tid * 4 + 3];
        scores_part[(size_t)(brow + tid) * 8 + blockIdx.x] = t;
    }
}

// ---------------------------------------------------------------------------
// conversion kernels
// ---------------------------------------------------------------------------
__global__ void split_f32(const float* __restrict__ in, __nv_bfloat16* __restrict__ hi,
                          __nv_bfloat16* __restrict__ lo, int n4)
{
    int i = blockIdx.x * blockDim.x + threadIdx.x;
    if (i >= n4) return;
    float4 v = ((const float4*)in)[i];
    __nv_bfloat16 h0 = __float2bfloat16(v.x), h1 = __float2bfloat16(v.y);
    __nv_bfloat16 h2 = __float2bfloat16(v.z), h3 = __float2bfloat16(v.w);
    ((uint2*)hi)[i] = make_uint2(pack_bf2(__bfloat162float(h0), __bfloat162float(h1)),
                                 pack_bf2(__bfloat162float(h2), __bfloat162float(h3)));
    ((uint2*)lo)[i] = make_uint2(pack_bf2(v.x - __bfloat162float(h0), v.y - __bfloat162float(h1)),
                                 pack_bf2(v.z - __bfloat162float(h2), v.w - __bfloat162float(h3)));
}

__global__ void transpose_split(const float* __restrict__ in,
                                __nv_bfloat16* __restrict__ hi,
                                __nv_bfloat16* __restrict__ lo, int K, int N)
{
    __shared__ float t[32][33];
    const int n0 = blockIdx.x * 32, k0 = blockIdx.y * 32;
    const int tx = threadIdx.x, ty = threadIdx.y;
#pragma unroll
    for (int i = 0; i < 32; i += 8)
        t[ty + i][tx] = in[(size_t)(k0 + ty + i) * N + n0 + tx];
    __syncthreads();
#pragma unroll
    for (int i = 0; i < 32; i += 8) {
        float v = t[tx][ty + i];
        __nv_bfloat16 h = __float2bfloat16(v);
        const size_t o = (size_t)(n0 + ty + i) * K + k0 + tx;
        hi[o] = h;
        lo[o] = __float2bfloat16(v - __bfloat162float(h));
    }
}

__global__ void bfused_kernel(const float* __restrict__ bg, const float* __restrict__ Gs,
                              const float* __restrict__ bgs, float* __restrict__ out,
                              int K, int N)
{
    __shared__ float red[8][32];
    const int c  = threadIdx.x & 31;
    const int kg = threadIdx.x >> 5;
    const int n  = blockIdx.x * 32 + c;
    const int kslice = K / 8;
    float acc = 0.0f;
    const float* p = Gs + (size_t)(kg * kslice) * N + n;
#pragma unroll 8
    for (int k = 0; k < kslice; k++)
        acc = fmaf(bg[kg * kslice + k], p[(size_t)k * N], acc);
    red[kg][c] = acc;
    __syncthreads();
    if (kg == 0) {
        float s = bgs[n];
#pragma unroll
        for (int i = 0; i < 8; i++) s += red[i][c];
        out[n] = s;
    }
}

__global__ void dec_proj(const float* __restrict__ sth, const float* __restrict__ W,
                         const float* __restrict__ bias, float* __restrict__ out)
{
    __shared__ float s[1024];
    const int b = blockIdx.y;
    const int col = blockIdx.x * 128 + threadIdx.x;
    for (int k = threadIdx.x; k < 1024; k += 128) s[k] = sth[b * 1024 + k];
    __syncthreads();
    float acc = 0.0f;
#pragma unroll 16
    for (int k = 0; k < 1024; k++) acc = fmaf(s[k], W[(size_t)k * 1024 + col], acc);
    out[b * 1024 + col] = acc + bias[col];
}

// ---------------------------------------------------------------------------
// attention tail
// ---------------------------------------------------------------------------
// One block per batch; T <= 256. Sums the 8 score partials, then softmax.
__global__ void softmax_kernel(const float* __restrict__ scores_part,
                               const float* __restrict__ cov,
                               float* __restrict__ alpha,
                               float* __restrict__ out_cov,
                               float* __restrict__ out_alpha, int T)
{
    const int b = blockIdx.x;
    const int tid = threadIdx.x;
    __shared__ float sc[256];
    __shared__ float red[256];

    float myv = -1e30f;
    if (tid < T) {
        const float4* p = (const float4*)(scores_part + (size_t)(b * T + tid) * 8);
        float4 x = p[0], y = p[1];
        myv = (x.x + x.y + x.z + x.w) + (y.x + y.y + y.z + y.w);
        sc[tid] = myv;
    }
    red[tid] = myv;
    __syncthreads();
    for (int off = 128; off > 0; off >>= 1) {
        if (tid < off) red[tid] = fmaxf(red[tid], red[tid + off]);
        __syncthreads();
    }
    const float m = red[0];
    __syncthreads();
    float e = 0.0f;
    if (tid < T) e = expf(sc[tid] - m);
    red[tid] = e;
    __syncthreads();
    for (int off = 128; off > 0; off >>= 1) {
        if (tid < off) red[tid] += red[tid + off];
        __syncthreads();
    }
    const float inv = 1.0f / red[0];
    if (tid < T) {
        float a = e * inv;
        alpha[b * T + tid]     = a;
        out_alpha[b * T + tid] = a;
        out_cov[b * T + tid]   = cov[b * T + tid] + a;
    }
}

__global__ void context_kernel(const float* __restrict__ alpha,
                               const float* __restrict__ Gstar,
                               float* __restrict__ out_c, int T, int DH)
{
    const int b = blockIdx.x;
    const int d = blockIdx.y * 128 + threadIdx.x;
    __shared__ float a_s[256];
    for (int t = threadIdx.x; t < T; t += blockDim.x) a_s[t] = alpha[b * T + t];
    __syncthreads();
    const float* gbase = Gstar + (size_t)b * T * DH + d;
    float acc = 0.0f;
#pragma unroll 4
    for (int t = 0; t < T; t++)
        acc = fmaf(a_s[t], gbase[(size_t)t * DH], acc);
    out_c[(size_t)b * DH + d] = acc;
}

// ---------------------------------------------------------------------------
extern "C" void kernel_launch(void* const* d_in, const int* in_sizes, int n_in,
                              void* d_out, int out_size)
{
    const float* gf   = (const float*)d_in[0];
    const float* sth  = (const float*)d_in[1];
    const float* cov  = (const float*)d_in[2];
    const float* Wg   = (const float*)d_in[3];
    const float* bg   = (const float*)d_in[4];
    const float* Gs   = (const float*)d_in[5];
    const float* bgs  = (const float*)d_in[6];
    const float* Wgs  = (const float*)d_in[7];
    const float* Wdec = (const float*)d_in[8];
    const float* bdec = (const float*)d_in[9];
    const float* v    = (const float*)d_in[10];

    const int GFD = in_sizes[4];        // 4096
    const int DH  = in_sizes[9];        // 1024
    const int b   = in_sizes[1] / DH;   // 32
    const int T   = in_sizes[2] / b;    // 196
    const int M   = b * T;              // 6272

    __nv_bfloat16 *gf_hi, *gf_lo, *Wg_hi, *Wg_lo, *GsT_hi, *GsT_lo;
    __nv_bfloat16 *WfT_hi, *WfT_lo, *WgsT_hi, *WgsT_lo, *Gstar_hi, *Gstar_lo;
    float *Gstar, *bfused, *dec, *scores_part, *alpha;
    cudaGetSymbolAddress((void**)&gf_hi, g_gf_hi);
    cudaGetSymbolAddress((void**)&gf_lo, g_gf_lo);
    cudaGetSymbolAddress((void**)&Wg_hi, g_Wg_hi);
    cudaGetSymbolAddress((void**)&Wg_lo, g_Wg_lo);
    cudaGetSymbolAddress((void**)&GsT_hi, g_GsT_hi);
    cudaGetSymbolAddress((void**)&GsT_lo, g_GsT_lo);
    cudaGetSymbolAddress((void**)&WfT_hi, g_WfT_hi);
    cudaGetSymbolAddress((void**)&WfT_lo, g_WfT_lo);
    cudaGetSymbolAddress((void**)&WgsT_hi, g_WgsT_hi);
    cudaGetSymbolAddress((void**)&WgsT_lo, g_WgsT_lo);
    cudaGetSymbolAddress((void**)&Gstar, g_Gstar);
    cudaGetSymbolAddress((void**)&Gstar_hi, g_Gstar_hi);
    cudaGetSymbolAddress((void**)&Gstar_lo, g_Gstar_lo);
    cudaGetSymbolAddress((void**)&bfused, g_bfused);
    cudaGetSymbolAddress((void**)&dec, g_dec);
    cudaGetSymbolAddress((void**)&scores_part, g_scores_part);
    cudaGetSymbolAddress((void**)&alpha, g_alpha);

    cudaFuncSetAttribute(tc_gemm, cudaFuncAttributeMaxDynamicSharedMemorySize, GEMM_SMEM);
    cudaFuncSetAttribute(tc_gemm_scores, cudaFuncAttributeMaxDynamicSharedMemorySize, GEMM_SMEM);

    // operand prep
    split_f32<<<(M * GFD / 4 + 255) / 256, 256>>>(gf, gf_hi, gf_lo, M * GFD / 4);
    split_f32<<<(GFD * GFD / 4 + 255) / 256, 256>>>(Wg, Wg_hi, Wg_lo, GFD * GFD / 4);
    transpose_split<<<dim3(DH / 32, GFD / 32), dim3(32, 8)>>>(Gs, GsT_hi, GsT_lo, GFD, DH);
    transpose_split<<<dim3(DH / 32, DH / 32), dim3(32, 8)>>>(Wgs, WgsT_hi, WgsT_lo, DH, DH);
    bfused_kernel<<<DH / 32, 256>>>(bg, Gs, bgs, bfused, GFD, DH);
    dec_proj<<<dim3(DH / 128, b), 128>>>(sth, Wdec, bdec, dec);

    // WfT[n,m] = sum_k Gs[k,n] * Wg[m,k]
    tc_gemm<<<dim3(GFD / 128, DH / 128), 256, GEMM_SMEM>>>(
        GsT_hi, GsT_lo, Wg_hi, Wg_lo, nullptr, nullptr, WfT_hi, WfT_lo, DH, GFD, GFD);
    // g_star = gf @ Wf + bfused
    tc_gemm<<<dim3(DH / 128, M / 128), 256, GEMM_SMEM>>>(
        gf_hi, gf_lo, WfT_hi, WfT_lo, bfused, Gstar, Gstar_hi, Gstar_lo, M, DH, GFD);
    // wgs = g_star @ Wgs, fused into score partials
    tc_gemm_scores<<<dim3(DH / 128, M / 128), 256, GEMM_SMEM>>>(
        Gstar_hi, Gstar_lo, WgsT_hi, WgsT_lo, dec, cov, v, scores_part, M, DH, DH, T);

    float* out_c     = (float*)d_out;
    float* out_cov   = out_c + (size_t)b * DH;
    float* out_alpha = out_cov + (size_t)b * T;
    softmax_kernel<<<b, 256>>>(scores_part, cov, alpha, out_cov, out_alpha, T);
    context_kernel<<<dim3(b, DH / 128), 128>>>(alpha, Gstar, out_c, T, DH);
}

// round 10
// speedup vs baseline: 1.0365x; 1.0015x over previous
#include <cuda_runtime.h>
#include <cuda_bf16.h>
#include <cstdint>
#include <math.h>

// ---------------------------------------------------------------------------
// img_attention, mma.sync (HMMA) split-bf16 path, fused-weight algebra:
//   WfT    = (Wg @ Gs)^T            [1024, 4096]
//   bfused = bg @ Gs + bgs          [1024]
//   g_star = gf @ Wf + bfused       [M, 1024]
//   wgs    = g_star @ Wgs  (fused into scores partials, never materialized)
//   dec    = s_t_hat @ Wdec + bdec  [32, 1024]
//   scores = tanh(wgs + dec + cov) @ v; alpha = softmax_T; c = alpha @ g_star
// Output: [c_img (b*DH) | coverage_new (b*T) | alpha (b*T)]
// ---------------------------------------------------------------------------

// ---- scratch (__device__ globals; allocation-free rule) ----
__device__ __align__(1024) __nv_bfloat16 g_gf_hi[25690112];
__device__ __align__(1024) __nv_bfloat16 g_gf_lo[25690112];
__device__ __align__(1024) __nv_bfloat16 g_Wg_hi[16777216];
__device__ __align__(1024) __nv_bfloat16 g_Wg_lo[16777216];
__device__ __align__(1024) __nv_bfloat16 g_GsT_hi[4194304];
__device__ __align__(1024) __nv_bfloat16 g_GsT_lo[4194304];
__device__ __align__(1024) __nv_bfloat16 g_WfT_hi[4194304];
__device__ __align__(1024) __nv_bfloat16 g_WfT_lo[4194304];
__device__ __align__(1024) __nv_bfloat16 g_WgsT_hi[1048576];
__device__ __align__(1024) __nv_bfloat16 g_WgsT_lo[1048576];
__device__ __align__(1024) float g_Gstar[6422528];
__device__ __align__(1024) __nv_bfloat16 g_Gstar_hi[6422528];
__device__ __align__(1024) __nv_bfloat16 g_Gstar_lo[6422528];
__device__ __align__(1024) float g_bfused[1024];
__device__ __align__(1024) float g_dec[32768];
__device__ __align__(1024) float g_scores_part[50176];   // [M][8]
__device__ __align__(1024) float g_alpha[6272];

// ---------------------------------------------------------------------------
// helpers
// ---------------------------------------------------------------------------
__device__ __forceinline__ uint32_t smem_u32(const void* p) {
    uint32_t a;
    asm("{ .reg .u64 t; cvta.to.shared.u64 t, %1; cvt.u32.u64 %0, t; }" : "=r"(a) : "l"(p));
    return a;
}
__device__ __forceinline__ void cp16(uint32_t s, const void* g) {
    asm volatile("cp.async.cg.shared.global [%0], [%1], 16;" :: "r"(s), "l"(g));
}
__device__ __forceinline__ void ldsm4(uint32_t* r, uint32_t a) {
    asm volatile("ldmatrix.sync.aligned.m8n8.x4.shared.b16 {%0,%1,%2,%3}, [%4];"
                 : "=r"(r[0]), "=r"(r[1]), "=r"(r[2]), "=r"(r[3]) : "r"(a));
}
__device__ __forceinline__ void mma16816(float* d, const uint32_t* a, const uint32_t* b) {
    asm volatile(
        "mma.sync.aligned.m16n8k16.row.col.f32.bf16.bf16.f32 "
        "{%0,%1,%2,%3}, {%4,%5,%6,%7}, {%8,%9}, {%0,%1,%2,%3};"
        : "+f"(d[0]), "+f"(d[1]), "+f"(d[2]), "+f"(d[3])
        : "r"(a[0]), "r"(a[1]), "r"(a[2]), "r"(a[3]), "r"(b[0]), "r"(b[1]));
}
__device__ __forceinline__ uint32_t pack_bf2(float x, float y) {
    __nv_bfloat162 h = __floats2bfloat162_rn(x, y);
    return *(uint32_t*)&h;
}

// MUFU-free tanh (FMA poly exp2 + Newton reciprocal), abs err ~3e-6.
__device__ __forceinline__ float tanh_fma(float x) {
    float ax = fminf(fabsf(x), 9.0f);
    float y  = -2.88539008f * ax;
    float nf = rintf(y);
    float f  = y - nf;
    float p  = 1.33335581e-3f;
    p = fmaf(p, f, 9.61812910e-3f);
    p = fmaf(p, f, 5.55041087e-2f);
    p = fmaf(p, f, 2.40226507e-1f);
    p = fmaf(p, f, 6.93147181e-1f);
    p = fmaf(p, f, 1.0f);
    int ni = (int)nf;
    float u = __int_as_float(__float_as_int(p) + (ni << 23));
    float d = 1.0f + u;
    float r = fmaf(-0.5f, d, 1.45711f);
    r = r * fmaf(-d, r, 2.0f);
    r = r * fmaf(-d, r, 2.0f);
    r = r * fmaf(-d, r, 2.0f);
    return copysignf((1.0f - u) * r, x);
}

// ---------------------------------------------------------------------------
// HMMA GEMM (BN=128): C[M,N] = A[M,K] @ B^T, split-bf16 3xMMA.
// BM=128, BN=128, BK=64, 3-stage cp.async, 8 warps (2m x 4n), warp 64x32.
// Fragment double-buffering: ldsm for ks+1 issued before MMAs of ks.
// ---------------------------------------------------------------------------
#define BKT 64
#define OP_BYTES (128 * 64 * 2)          // 16 KB per operand tile
#define STG_BYTES (4 * OP_BYTES)         // 64 KB per stage
#define GEMM_SMEM (3 * STG_BYTES)        // 192 KB

__device__ __forceinline__ void load_stage(uint32_t stg,
    const __nv_bfloat16* __restrict__ Ah, const __nv_bfloat16* __restrict__ Al,
    const __nv_bfloat16* __restrict__ Bh, const __nv_bfloat16* __restrict__ Bl,
    int brow, int bcol, int K, int k0, int tid)
{
#pragma unroll
    for (int op = 0; op < 4; op++) {
        const __nv_bfloat16* P = (op == 0) ? Ah : (op == 1) ? Al : (op == 2) ? Bh : Bl;
        const int row0 = (op < 2) ? brow : bcol;
#pragma unroll
        for (int it = 0; it < 4; it++) {
            int idx = tid + it * 256;
            int r = idx >> 3, c = idx & 7;
            uint32_t dst = stg + op * OP_BYTES + r * 128 + (((uint32_t)(c ^ (r & 7))) << 4);
            cp16(dst, P + (size_t)(row0 + r) * K + k0 + c * 8);
        }
    }
}

// Load all warp fragments for k-subtile ks into register buffer `buf`.
#define LOAD_FRAGS(buf, ks)                                                    \
    {                                                                          \
        const uint32_t cA = ((uint32_t)(((ks) * 2 + hiA) ^ phA)) << 4;         \
        const uint32_t cB = ((uint32_t)(((ks) * 2 + hiB) ^ phB)) << 4;         \
        _Pragma("unroll")                                                      \
        for (int mt = 0; mt < 4; mt++) {                                       \
            uint32_t ro = (uint32_t)(rowA + mt * 16) * 128 + cA;               \
            ldsm4(ah[buf][mt], aH + ro);                                       \
            ldsm4(al[buf][mt], aL + ro);                                       \
        }                                                                      \
        _Pragma("unroll")                                                      \
        for (int p = 0; p < 2; p++) {                                          \
            uint32_t ro = (uint32_t)(rowB + p * 16) * 128 + cB;                \
            ldsm4(bh[buf][p], bH + ro);                                        \
            ldsm4(bl[buf][p], bL + ro);                                        \
        }                                                                      \
    }

#define DO_MMAS(buf)                                                           \
    _Pragma("unroll")                                                          \
    for (int mt = 0; mt < 4; mt++)                                             \
        _Pragma("unroll")                                                      \
        for (int nt = 0; nt < 4; nt++) {                                       \
            float* d = acc[mt][nt];                                            \
            const uint32_t* bhf = &bh[buf][nt >> 1][(nt & 1) * 2];             \
            const uint32_t* blf = &bl[buf][nt >> 1][(nt & 1) * 2];             \
            mma16816(d, ah[buf][mt], bhf);                                     \
            mma16816(d, ah[buf][mt], blf);                                     \
            mma16816(d, al[buf][mt], bhf);                                     \
        }

// Shared mainloop: leaves acc[][][] with final fp32 results.
#define GEMM_MAINLOOP()                                                        \
    load_stage(sbase, Ahi, Alo, Bhi, Blo, brow, bcol, K, 0, tid);              \
    asm volatile("cp.async.commit_group;" ::: "memory");                       \
    if (KT > 1) {                                                              \
        load_stage(sbase + STG_BYTES, Ahi, Alo, Bhi, Blo, brow, bcol, K, BKT, tid); \
        asm volatile("cp.async.commit_group;" ::: "memory");                   \
    }                                                                          \
    for (int kt = 0; kt < KT; kt++) {                                          \
        if (kt + 1 < KT) asm volatile("cp.async.wait_group 1;" ::: "memory");  \
        else             asm volatile("cp.async.wait_group 0;" ::: "memory");  \
        __syncthreads();                                                       \
        const uint32_t stg = sbase + (kt % 3) * STG_BYTES;                     \
        const uint32_t aH = stg, aL = stg + OP_BYTES;                          \
        const uint32_t bH = stg + 2 * OP_BYTES, bL = stg + 3 * OP_BYTES;       \
        uint32_t ah[2][4][4], al[2][4][4], bh[2][2][4], bl[2][2][4];           \
        LOAD_FRAGS(0, 0);                                                      \
        _Pragma("unroll")                                                      \
        for (int ks = 0; ks < 4; ks++) {                                       \
            if (ks < 3) { LOAD_FRAGS((ks + 1) & 1, ks + 1); }                  \
            DO_MMAS(ks & 1);                                                   \
        }                                                                      \
        if (kt + 2 < KT) {                                                     \
            load_stage(sbase + ((kt + 2) % 3) * STG_BYTES,                     \
                       Ahi, Alo, Bhi, Blo, brow, bcol, K, (kt + 2) * BKT, tid);\
            asm volatile("cp.async.commit_group;" ::: "memory");               \
        }                                                                      \
    }

#define GEMM_PREAMBLE()                                                        \
    extern __shared__ __align__(128) char smem[];                              \
    const uint32_t sbase = smem_u32(smem);                                     \
    const int tid = threadIdx.x, wid = tid >> 5, lane = tid & 31;              \
    const int wm = wid >> 2, wn = wid & 3;                                     \
    const int brow = blockIdx.y * 128, bcol = blockIdx.x * 128;                \
    const int KT = K / BKT;                                                    \
    const int rowA = wm * 64 + (lane & 15);                                    \
    const int phA  = rowA & 7;                                                 \
    const int hiA  = lane >> 4;                                                \
    const int rowB = wn * 32 + ((lane >> 4) << 3) + (lane & 7);                \
    const int phB  = lane & 7;                                                 \
    const int hiB  = (lane >> 3) & 1;                                          \
    float acc[4][4][4];                                                        \
    _Pragma("unroll")                                                          \
    for (int mt = 0; mt < 4; mt++)                                             \
        _Pragma("unroll")                                                      \
        for (int nt = 0; nt < 4; nt++)                                         \
            _Pragma("unroll")                                                  \
            for (int j = 0; j < 4; j++) acc[mt][nt][j] = 0.0f;

__global__ __launch_bounds__(256, 1)
void tc_gemm(const __nv_bfloat16* __restrict__ Ahi, const __nv_bfloat16* __restrict__ Alo,
             const __nv_bfloat16* __restrict__ Bhi, const __nv_bfloat16* __restrict__ Blo,
             const float* __restrict__ bias,
             float* __restrict__ Cf, __nv_bfloat16* __restrict__ Chi,
             __nv_bfloat16* __restrict__ Clo,
             int M, int N, int K)
{
    GEMM_PREAMBLE();
    GEMM_MAINLOOP();

#pragma unroll
    for (int mt = 0; mt < 4; mt++)
#pragma unroll
        for (int nt = 0; nt < 4; nt++) {
            const int r0 = brow + wm * 64 + mt * 16 + (lane >> 2);
            const int c0 = bcol + wn * 32 + nt * 8 + (lane & 3) * 2;
            float v0 = acc[mt][nt][0], v1 = acc[mt][nt][1];
            float v2 = acc[mt][nt][2], v3 = acc[mt][nt][3];
            if (bias) {
                float b0 = bias[c0], b1 = bias[c0 + 1];
                v0 += b0; v1 += b1; v2 += b0; v3 += b1;
            }
            const size_t o0 = (size_t)r0 * N + c0;
            const size_t o1 = (size_t)(r0 + 8) * N + c0;
            if (Cf) {
                *(float2*)&Cf[o0] = make_float2(v0, v1);
                *(float2*)&Cf[o1] = make_float2(v2, v3);
            }
            if (Chi) {
                __nv_bfloat16 h0 = __float2bfloat16(v0), h1 = __float2bfloat16(v1);
                __nv_bfloat16 h2 = __float2bfloat16(v2), h3 = __float2bfloat16(v3);
                *(uint32_t*)&Chi[o0] = pack_bf2(__bfloat162float(h0), __bfloat162float(h1));
                *(uint32_t*)&Chi[o1] = pack_bf2(__bfloat162float(h2), __bfloat162float(h3));
                *(uint32_t*)&Clo[o0] = pack_bf2(v0 - __bfloat162float(h0), v1 - __bfloat162float(h1));
                *(uint32_t*)&Clo[o1] = pack_bf2(v2 - __bfloat162float(h2), v3 - __bfloat162float(h3));
            }
        }
}

// ---------------------------------------------------------------------------
// GEMM3 fused: wgs tile -> tanh(wgs + dec + cov) * v, reduced over this CTA's
// 128 columns -> scores_part[row][blockIdx.x].
// ---------------------------------------------------------------------------
__global__ __launch_bounds__(256, 1)
void tc_gemm_scores(const __nv_bfloat16* __restrict__ Ahi, const __nv_bfloat16* __restrict__ Alo,
                    const __nv_bfloat16* __restrict__ Bhi, const __nv_bfloat16* __restrict__ Blo,
                    const float* __restrict__ dec, const float* __restrict__ cov,
                    const float* __restrict__ vvec, float* __restrict__ scores_part,
                    int M, int N, int K, int T)
{
    GEMM_PREAMBLE();
    GEMM_MAINLOOP();

    __syncthreads();                    // smem stages now reusable as scratch
    float* red = (float*)smem;          // [128][4]

#pragma unroll
    for (int mt = 0; mt < 4; mt++) {
        const int rl0 = wm * 64 + mt * 16 + (lane >> 2);
        const int rl1 = rl0 + 8;
        const int gr0 = brow + rl0, gr1 = brow + rl1;
        const float cov0 = cov[gr0], cov1 = cov[gr1];
        const float* dec0 = dec + (size_t)(gr0 / T) * 1024;
        const float* dec1 = dec + (size_t)(gr1 / T) * 1024;
        float s0 = 0.0f, s1 = 0.0f;
#pragma unroll
        for (int nt = 0; nt < 4; nt++) {
            const int c0 = bcol + wn * 32 + nt * 8 + (lane & 3) * 2;
            const float va = vvec[c0], vb = vvec[c0 + 1];
            const float da = dec0[c0], db = dec0[c0 + 1];
            const float ea = dec1[c0], eb = dec1[c0 + 1];
            s0 += tanh_fma(acc[mt][nt][0] + da + cov0) * va
                + tanh_fma(acc[mt][nt][1] + db + cov0) * vb;
            s1 += tanh_fma(acc[mt][nt][2] + ea + cov1) * va
                + tanh_fma(acc[mt][nt][3] + eb + cov1) * vb;
        }
        s0 += __shfl_xor_sync(0xffffffffu, s0, 1);
        s0 += __shfl_xor_sync(0xffffffffu, s0, 2);
        s1 += __shfl_xor_sync(0xffffffffu, s1, 1);
        s1 += __shfl_xor_sync(0xffffffffu, s1, 2);
        if ((lane & 3) == 0) {
            red[rl0 * 4 + wn] = s0;
            red[rl1 * 4 + wn] = s1;
        }
    }
    __syncthreads();
    if (tid < 128) {
        float t = red[tid * 4] + red[tid * 4 + 1] + red[tid * 4 + 2] + red[tid * 4 + 3];
        scores_part[(size_t)(brow + tid) * 8 + blockIdx.x] = t;
    }
}

// ---------------------------------------------------------------------------
// conversion kernels
// ---------------------------------------------------------------------------
__global__ void split_f32(const float* __restrict__ in, __nv_bfloat16* __restrict__ hi,
                          __nv_bfloat16* __restrict__ lo, int n4)
{
    int i = blockIdx.x * blockDim.x + threadIdx.x;
    if (i >= n4) return;
    float4 v = ((const float4*)in)[i];
    __nv_bfloat16 h0 = __float2bfloat16(v.x), h1 = __float2bfloat16(v.y);
    __nv_bfloat16 h2 = __float2bfloat16(v.z), h3 = __float2bfloat16(v.w);
    ((uint2*)hi)[i] = make_uint2(pack_bf2(__bfloat162float(h0), __bfloat162float(h1)),
                                 pack_bf2(__bfloat162float(h2), __bfloat162float(h3)));
    ((uint2*)lo)[i] = make_uint2(pack_bf2(v.x - __bfloat162float(h0), v.y - __bfloat162float(h1)),
                                 pack_bf2(v.z - __bfloat162float(h2), v.w - __bfloat162float(h3)));
}

__global__ void transpose_split(const float* __restrict__ in,
                                __nv_bfloat16* __restrict__ hi,
                                __nv_bfloat16* __restrict__ lo, int K, int N)
{
    __shared__ float t[32][33];
    const int n0 = blockIdx.x * 32, k0 = blockIdx.y * 32;
    const int tx = threadIdx.x, ty = threadIdx.y;
#pragma unroll
    for (int i = 0; i < 32; i += 8)
        t[ty + i][tx] = in[(size_t)(k0 + ty + i) * N + n0 + tx];
    __syncthreads();
#pragma unroll
    for (int i = 0; i < 32; i += 8) {
        float v = t[tx][ty + i];
        __nv_bfloat16 h = __float2bfloat16(v);
        const size_t o = (size_t)(n0 + ty + i) * K + k0 + tx;
        hi[o] = h;
        lo[o] = __float2bfloat16(v - __bfloat162float(h));
    }
}

__global__ void bfused_kernel(const float* __restrict__ bg, const float* __restrict__ Gs,
                              const float* __restrict__ bgs, float* __restrict__ out,
                              int K, int N)
{
    __shared__ float red[8][32];
    const int c  = threadIdx.x & 31;
    const int kg = threadIdx.x >> 5;
    const int n  = blockIdx.x * 32 + c;
    const int kslice = K / 8;
    float acc = 0.0f;
    const float* p = Gs + (size_t)(kg * kslice) * N + n;
#pragma unroll 8
    for (int k = 0; k < kslice; k++)
        acc = fmaf(bg[kg * kslice + k], p[(size_t)k * N], acc);
    red[kg][c] = acc;
    __syncthreads();
    if (kg == 0) {
        float s = bgs[n];
#pragma unroll
        for (int i = 0; i < 8; i++) s += red[i][c];
        out[n] = s;
    }
}

__global__ void dec_proj(const float* __restrict__ sth, const float* __restrict__ W,
                         const float* __restrict__ bias, float* __restrict__ out)
{
    __shared__ float s[1024];
    const int b = blockIdx.y;
    const int col = blockIdx.x * 128 + threadIdx.x;
    for (int k = threadIdx.x; k < 1024; k += 128) s[k] = sth[b * 1024 + k];
    __syncthreads();
    float acc = 0.0f;
#pragma unroll 16
    for (int k = 0; k < 1024; k++) acc = fmaf(s[k], W[(size_t)k * 1024 + col], acc);
    out[b * 1024 + col] = acc + bias[col];
}

// ---------------------------------------------------------------------------
// attention tail
// ---------------------------------------------------------------------------
__global__ void softmax_kernel(const float* __restrict__ scores_part,
                               const float* __restrict__ cov,
                               float* __restrict__ alpha,
                               float* __restrict__ out_cov,
                               float* __restrict__ out_alpha, int T)
{
    const int b = blockIdx.x;
    const int tid = threadIdx.x;
    __shared__ float sc[256];
    __shared__ float red[256];

    float myv = -1e30f;
    if (tid < T) {
        const float4* p = (const float4*)(scores_part + (size_t)(b * T + tid) * 8);
        float4 x = p[0], y = p[1];
        myv = (x.x + x.y + x.z + x.w) + (y.x + y.y + y.z + y.w);
        sc[tid] = myv;
    }
    red[tid] = myv;
    __syncthreads();
    for (int off = 128; off > 0; off >>= 1) {
        if (tid < off) red[tid] = fmaxf(red[tid], red[tid + off]);
        __syncthreads();
    }
    const float m = red[0];
    __syncthreads();
    float e = 0.0f;
    if (tid < T) e = expf(sc[tid] - m);
    red[tid] = e;
    __syncthreads();
    for (int off = 128; off > 0; off >>= 1) {
        if (tid < off) red[tid] += red[tid + off];
        __syncthreads();
    }
    const float inv = 1.0f / red[0];
    if (tid < T) {
        float a = e * inv;
        alpha[b * T + tid]     = a;
        out_alpha[b * T + tid] = a;
        out_cov[b * T + tid]   = cov[b * T + tid] + a;
    }
}

__global__ void context_kernel(const float* __restrict__ alpha,
                               const float* __restrict__ Gstar,
                               float* __restrict__ out_c, int T, int DH)
{
    const int b = blockIdx.x;
    const int d = blockIdx.y * 128 + threadIdx.x;
    __shared__ float a_s[256];
    for (int t = threadIdx.x; t < T; t += blockDim.x) a_s[t] = alpha[b * T + t];
    __syncthreads();
    const float* gbase = Gstar + (size_t)b * T * DH + d;
    float acc = 0.0f;
#pragma unroll 4
    for (int t = 0; t < T; t++)
        acc = fmaf(a_s[t], gbase[(size_t)t * DH], acc);
    out_c[(size_t)b * DH + d] = acc;
}

// ---------------------------------------------------------------------------
extern "C" void kernel_launch(void* const* d_in, const int* in_sizes, int n_in,
                              void* d_out, int out_size)
{
    const float* gf   = (const float*)d_in[0];
    const float* sth  = (const float*)d_in[1];
    const float* cov  = (const float*)d_in[2];
    const float* Wg   = (const float*)d_in[3];
    const float* bg   = (const float*)d_in[4];
    const float* Gs   = (const float*)d_in[5];
    const float* bgs  = (const float*)d_in[6];
    const float* Wgs  = (const float*)d_in[7];
    const float* Wdec = (const float*)d_in[8];
    const float* bdec = (const float*)d_in[9];
    const float* v    = (const float*)d_in[10];

    const int GFD = in_sizes[4];        // 4096
    const int DH  = in_sizes[9];        // 1024
    const int b   = in_sizes[1] / DH;   // 32
    const int T   = in_sizes[2] / b;    // 196
    const int M   = b * T;              // 6272

    __nv_bfloat16 *gf_hi, *gf_lo, *Wg_hi, *Wg_lo, *GsT_hi, *GsT_lo;
    __nv_bfloat16 *WfT_hi, *WfT_lo, *WgsT_hi, *WgsT_lo, *Gstar_hi, *Gstar_lo;
    float *Gstar, *bfused, *dec, *scores_part, *alpha;
    cudaGetSymbolAddress((void**)&gf_hi, g_gf_hi);
    cudaGetSymbolAddress((void**)&gf_lo, g_gf_lo);
    cudaGetSymbolAddress((void**)&Wg_hi, g_Wg_hi);
    cudaGetSymbolAddress((void**)&Wg_lo, g_Wg_lo);
    cudaGetSymbolAddress((void**)&GsT_hi, g_GsT_hi);
    cudaGetSymbolAddress((void**)&GsT_lo, g_GsT_lo);
    cudaGetSymbolAddress((void**)&WfT_hi, g_WfT_hi);
    cudaGetSymbolAddress((void**)&WfT_lo, g_WfT_lo);
    cudaGetSymbolAddress((void**)&WgsT_hi, g_WgsT_hi);
    cudaGetSymbolAddress((void**)&WgsT_lo, g_WgsT_lo);
    cudaGetSymbolAddress((void**)&Gstar, g_Gstar);
    cudaGetSymbolAddress((void**)&Gstar_hi, g_Gstar_hi);
    cudaGetSymbolAddress((void**)&Gstar_lo, g_Gstar_lo);
    cudaGetSymbolAddress((void**)&bfused, g_bfused);
    cudaGetSymbolAddress((void**)&dec, g_dec);
    cudaGetSymbolAddress((void**)&scores_part, g_scores_part);
    cudaGetSymbolAddress((void**)&alpha, g_alpha);

    cudaFuncSetAttribute(tc_gemm, cudaFuncAttributeMaxDynamicSharedMemorySize, GEMM_SMEM);
    cudaFuncSetAttribute(tc_gemm_scores, cudaFuncAttributeMaxDynamicSharedMemorySize, GEMM_SMEM);

    // operand prep
    split_f32<<<(M * GFD / 4 + 255) / 256, 256>>>(gf, gf_hi, gf_lo, M * GFD / 4);
    split_f32<<<(GFD * GFD / 4 + 255) / 256, 256>>>(Wg, Wg_hi, Wg_lo, GFD * GFD / 4);
    transpose_split<<<dim3(DH / 32, GFD / 32), dim3(32, 8)>>>(Gs, GsT_hi, GsT_lo, GFD, DH);
    transpose_split<<<dim3(DH / 32, DH / 32), dim3(32, 8)>>>(Wgs, WgsT_hi, WgsT_lo, DH, DH);
    bfused_kernel<<<DH / 32, 256>>>(bg, Gs, bgs, bfused, GFD, DH);
    dec_proj<<<dim3(DH / 128, b), 128>>>(sth, Wdec, bdec, dec);

    // WfT[n,m] = sum_k Gs[k,n] * Wg[m,k]
    tc_gemm<<<dim3(GFD / 128, DH / 128), 256, GEMM_SMEM>>>(
        GsT_hi, GsT_lo, Wg_hi, Wg_lo, nullptr, nullptr, WfT_hi, WfT_lo, DH, GFD, GFD);
    // g_star = gf @ Wf + bfused
    tc_gemm<<<dim3(DH / 128, M / 128), 256, GEMM_SMEM>>>(
        gf_hi, gf_lo, WfT_hi, WfT_lo, bfused, Gstar, Gstar_hi, Gstar_lo, M, DH, GFD);
    // wgs = g_star @ Wgs, fused into score partials
    tc_gemm_scores<<<dim3(DH / 128, M / 128), 256, GEMM_SMEM>>>(
        Gstar_hi, Gstar_lo, WgsT_hi, WgsT_lo, dec, cov, v, scores_part, M, DH, DH, T);

    float* out_c     = (float*)d_out;
    float* out_cov   = out_c + (size_t)b * DH;
    float* out_alpha = out_cov + (size_t)b * T;
    softmax_kernel<<<b, 256>>>(scores_part, cov, alpha, out_cov, out_alpha, T);
    context_kernel<<<dim3(b, DH / 128), 128>>>(alpha, Gstar, out_c, T, DH);
}

// round 12
// speedup vs baseline: 1.0421x; 1.0054x over previous
#include <cuda_runtime.h>
#include <cuda_bf16.h>
#include <cstdint>
#include <math.h>

// ---------------------------------------------------------------------------
// img_attention, mma.sync (HMMA) split-bf16 path, fused-weight algebra:
//   WfT    = (Wg @ Gs)^T            [1024, 4096]
//   bfused = bg @ Gs + bgs          [1024]
//   g_star = gf @ Wf + bfused       [M, 1024]
//   wgs    = g_star @ Wgs  (fused into scores partials, never materialized)
//   dec    = s_t_hat @ Wdec + bdec  [32, 1024]
//   scores = tanh(wgs + dec + cov) @ v; alpha = softmax_T; c = alpha @ g_star
// Output: [c_img (b*DH) | coverage_new (b*T) | alpha (b*T)]
// ---------------------------------------------------------------------------

// ---- scratch (__device__ globals; allocation-free rule) ----
__device__ __align__(1024) __nv_bfloat16 g_gf_hi[25690112];
__device__ __align__(1024) __nv_bfloat16 g_gf_lo[25690112];
__device__ __align__(1024) __nv_bfloat16 g_Wg_hi[16777216];
__device__ __align__(1024) __nv_bfloat16 g_Wg_lo[16777216];
__device__ __align__(1024) __nv_bfloat16 g_GsT_hi[4194304];
__device__ __align__(1024) __nv_bfloat16 g_GsT_lo[4194304];
__device__ __align__(1024) __nv_bfloat16 g_WfT_hi[4194304];
__device__ __align__(1024) __nv_bfloat16 g_WfT_lo[4194304];
__device__ __align__(1024) __nv_bfloat16 g_WgsT_hi[1048576];
__device__ __align__(1024) __nv_bfloat16 g_WgsT_lo[1048576];
__device__ __align__(1024) float g_Gstar[6422528];
__device__ __align__(1024) __nv_bfloat16 g_Gstar_hi[6422528];
__device__ __align__(1024) __nv_bfloat16 g_Gstar_lo[6422528];
__device__ __align__(1024) float g_bfused[1024];
__device__ __align__(1024) float g_dec[32768];
__device__ __align__(1024) float g_scores_part[50176];   // [M][8]

// ---------------------------------------------------------------------------
// helpers
// ---------------------------------------------------------------------------
__device__ __forceinline__ uint32_t smem_u32(const void* p) {
    uint32_t a;
    asm("{ .reg .u64 t; cvta.to.shared.u64 t, %1; cvt.u32.u64 %0, t; }" : "=r"(a) : "l"(p));
    return a;
}
__device__ __forceinline__ void cp16(uint32_t s, const void* g) {
    asm volatile("cp.async.cg.shared.global [%0], [%1], 16;" :: "r"(s), "l"(g));
}
__device__ __forceinline__ void ldsm4(uint32_t* r, uint32_t a) {
    asm volatile("ldmatrix.sync.aligned.m8n8.x4.shared.b16 {%0,%1,%2,%3}, [%4];"
                 : "=r"(r[0]), "=r"(r[1]), "=r"(r[2]), "=r"(r[3]) : "r"(a));
}
__device__ __forceinline__ void mma16816(float* d, const uint32_t* a, const uint32_t* b) {
    asm volatile(
        "mma.sync.aligned.m16n8k16.row.col.f32.bf16.bf16.f32 "
        "{%0,%1,%2,%3}, {%4,%5,%6,%7}, {%8,%9}, {%0,%1,%2,%3};"
        : "+f"(d[0]), "+f"(d[1]), "+f"(d[2]), "+f"(d[3])
        : "r"(a[0]), "r"(a[1]), "r"(a[2]), "r"(a[3]), "r"(b[0]), "r"(b[1]));
}
__device__ __forceinline__ uint32_t pack_bf2(float x, float y) {
    __nv_bfloat162 h = __floats2bfloat162_rn(x, y);
    return *(uint32_t*)&h;
}

// MUFU-free tanh (FMA poly exp2 + Newton reciprocal), abs err ~3e-6.
__device__ __forceinline__ float tanh_fma(float x) {
    float ax = fminf(fabsf(x), 9.0f);
    float y  = -2.88539008f * ax;
    float nf = rintf(y);
    float f  = y - nf;
    float p  = 1.33335581e-3f;
    p = fmaf(p, f, 9.61812910e-3f);
    p = fmaf(p, f, 5.55041087e-2f);
    p = fmaf(p, f, 2.40226507e-1f);
    p = fmaf(p, f, 6.93147181e-1f);
    p = fmaf(p, f, 1.0f);
    int ni = (int)nf;
    float u = __int_as_float(__float_as_int(p) + (ni << 23));
    float d = 1.0f + u;
    float r = fmaf(-0.5f, d, 1.45711f);
    r = r * fmaf(-d, r, 2.0f);
    r = r * fmaf(-d, r, 2.0f);
    r = r * fmaf(-d, r, 2.0f);
    return copysignf((1.0f - u) * r, x);
}

// ---------------------------------------------------------------------------
// HMMA GEMM (BN=128): C[M,N] = A[M,K] @ B^T, split-bf16 3xMMA.
// BM=128, BN=128, BK=64, 3-stage cp.async, 8 warps (2m x 4n), warp 64x32.
// ---------------------------------------------------------------------------
#define BKT 64
#define OP_BYTES (128 * 64 * 2)          // 16 KB per operand tile
#define STG_BYTES (4 * OP_BYTES)         // 64 KB per stage
#define GEMM_SMEM (3 * STG_BYTES)        // 192 KB

__device__ __forceinline__ void load_stage(uint32_t stg,
    const __nv_bfloat16* __restrict__ Ah, const __nv_bfloat16* __restrict__ Al,
    const __nv_bfloat16* __restrict__ Bh, const __nv_bfloat16* __restrict__ Bl,
    int brow, int bcol, int K, int k0, int tid)
{
#pragma unroll
    for (int op = 0; op < 4; op++) {
        const __nv_bfloat16* P = (op == 0) ? Ah : (op == 1) ? Al : (op == 2) ? Bh : Bl;
        const int row0 = (op < 2) ? brow : bcol;
#pragma unroll
        for (int it = 0; it < 4; it++) {
            int idx = tid + it * 256;
            int r = idx >> 3, c = idx & 7;
            uint32_t dst = stg + op * OP_BYTES + r * 128 + (((uint32_t)(c ^ (r & 7))) << 4);
            cp16(dst, P + (size_t)(row0 + r) * K + k0 + c * 8);
        }
    }
}

#define LOAD_FRAGS(buf, ks)                                                    \
    {                                                                          \
        const uint32_t cA = ((uint32_t)(((ks) * 2 + hiA) ^ phA)) << 4;         \
        const uint32_t cB = ((uint32_t)(((ks) * 2 + hiB) ^ phB)) << 4;         \
        _Pragma("unroll")                                                      \
        for (int mt = 0; mt < 4; mt++) {                                       \
            uint32_t ro = (uint32_t)(rowA + mt * 16) * 128 + cA;               \
            ldsm4(ah[buf][mt], aH + ro);                                       \
            ldsm4(al[buf][mt], aL + ro);                                       \
        }                                                                      \
        _Pragma("unroll")                                                      \
        for (int p = 0; p < 2; p++) {                                          \
            uint32_t ro = (uint32_t)(rowB + p * 16) * 128 + cB;                \
            ldsm4(bh[buf][p], bH + ro);                                        \
            ldsm4(bl[buf][p], bL + ro);                                        \
        }                                                                      \
    }

#define DO_MMAS(buf)                                                           \
    _Pragma("unroll")                                                          \
    for (int mt = 0; mt < 4; mt++)                                             \
        _Pragma("unroll")                                                      \
        for (int nt = 0; nt < 4; nt++) {                                       \
            float* d = acc[mt][nt];                                            \
            const uint32_t* bhf = &bh[buf][nt >> 1][(nt & 1) * 2];             \
            const uint32_t* blf = &bl[buf][nt >> 1][(nt & 1) * 2];             \
            mma16816(d, ah[buf][mt], bhf);                                     \
            mma16816(d, ah[buf][mt], blf);                                     \
            mma16816(d, al[buf][mt], bhf);                                     \
        }

#define GEMM_MAINLOOP()                                                        \
    load_stage(sbase, Ahi, Alo, Bhi, Blo, brow, bcol, K, 0, tid);              \
    asm volatile("cp.async.commit_group;" ::: "memory");                       \
    if (KT > 1) {                                                              \
        load_stage(sbase + STG_BYTES, Ahi, Alo, Bhi, Blo, brow, bcol, K, BKT, tid); \
        asm volatile("cp.async.commit_group;" ::: "memory");                   \
    }                                                                          \
    for (int kt = 0; kt < KT; kt++) {                                          \
        if (kt + 1 < KT) asm volatile("cp.async.wait_group 1;" ::: "memory");  \
        else             asm volatile("cp.async.wait_group 0;" ::: "memory");  \
        __syncthreads();                                                       \
        const uint32_t stg = sbase + (kt % 3) * STG_BYTES;                     \
        const uint32_t aH = stg, aL = stg + OP_BYTES;                          \
        const uint32_t bH = stg + 2 * OP_BYTES, bL = stg + 3 * OP_BYTES;       \
        uint32_t ah[2][4][4], al[2][4][4], bh[2][2][4], bl[2][2][4];           \
        LOAD_FRAGS(0, 0);                                                      \
        _Pragma("unroll")                                                      \
        for (int ks = 0; ks < 4; ks++) {                                       \
            if (ks < 3) { LOAD_FRAGS((ks + 1) & 1, ks + 1); }                  \
            DO_MMAS(ks & 1);                                                   \
        }                                                                      \
        if (kt + 2 < KT) {                                                     \
            load_stage(sbase + ((kt + 2) % 3) * STG_BYTES,                     \
                       Ahi, Alo, Bhi, Blo, brow, bcol, K, (kt + 2) * BKT, tid);\
            asm volatile("cp.async.commit_group;" ::: "memory");               \
        }                                                                      \
    }

#define GEMM_PREAMBLE()                                                        \
    extern __shared__ __align__(128) char smem[];                              \
    const uint32_t sbase = smem_u32(smem);                                     \
    const int tid = threadIdx.x, wid = tid >> 5, lane = tid & 31;              \
    const int wm = wid >> 2, wn = wid & 3;                                     \
    const int brow = blockIdx.y * 128, bcol = blockIdx.x * 128;                \
    const int KT = K / BKT;                                                    \
    const int rowA = wm * 64 + (lane & 15);                                    \
    const int phA  = rowA & 7;                                                 \
    const int hiA  = lane >> 4;                                                \
    const int rowB = wn * 32 + ((lane >> 4) << 3) + (lane & 7);                \
    const int phB  = lane & 7;                                                 \
    const int hiB  = (lane >> 3) & 1;                                          \
    float acc[4][4][4];                                                        \
    _Pragma("unroll")                                                          \
    for (int mt = 0; mt < 4; mt++)                                             \
        _Pragma("unroll")                                                      \
        for (int nt = 0; nt < 4; nt++)                                         \
            _Pragma("unroll")                                                  \
            for (int j = 0; j < 4; j++) acc[mt][nt][j] = 0.0f;

__global__ __launch_bounds__(256, 1)
void tc_gemm(const __nv_bfloat16* __restrict__ Ahi, const __nv_bfloat16* __restrict__ Alo,
             const __nv_bfloat16* __restrict__ Bhi, const __nv_bfloat16* __restrict__ Blo,
             const float* __restrict__ bias,
             float* __restrict__ Cf, __nv_bfloat16* __restrict__ Chi,
             __nv_bfloat16* __restrict__ Clo,
             int M, int N, int K)
{
    GEMM_PREAMBLE();
    GEMM_MAINLOOP();

#pragma unroll
    for (int mt = 0; mt < 4; mt++)
#pragma unroll
        for (int nt = 0; nt < 4; nt++) {
            const int r0 = brow + wm * 64 + mt * 16 + (lane >> 2);
            const int c0 = bcol + wn * 32 + nt * 8 + (lane & 3) * 2;
            float v0 = acc[mt][nt][0], v1 = acc[mt][nt][1];
            float v2 = acc[mt][nt][2], v3 = acc[mt][nt][3];
            if (bias) {
                float b0 = bias[c0], b1 = bias[c0 + 1];
                v0 += b0; v1 += b1; v2 += b0; v3 += b1;
            }
            const size_t o0 = (size_t)r0 * N + c0;
            const size_t o1 = (size_t)(r0 + 8) * N + c0;
            if (Cf) {
                *(float2*)&Cf[o0] = make_float2(v0, v1);
                *(float2*)&Cf[o1] = make_float2(v2, v3);
            }
            if (Chi) {
                __nv_bfloat16 h0 = __float2bfloat16(v0), h1 = __float2bfloat16(v1);
                __nv_bfloat16 h2 = __float2bfloat16(v2), h3 = __float2bfloat16(v3);
                *(uint32_t*)&Chi[o0] = pack_bf2(__bfloat162float(h0), __bfloat162float(h1));
                *(uint32_t*)&Chi[o1] = pack_bf2(__bfloat162float(h2), __bfloat162float(h3));
                *(uint32_t*)&Clo[o0] = pack_bf2(v0 - __bfloat162float(h0), v1 - __bfloat162float(h1));
                *(uint32_t*)&Clo[o1] = pack_bf2(v2 - __bfloat162float(h2), v3 - __bfloat162float(h3));
            }
        }
}

// ---------------------------------------------------------------------------
// GEMM3 fused: wgs tile -> tanh(wgs + dec + cov) * v, reduced over this CTA's
// 128 columns -> scores_part[row][blockIdx.x].
// ---------------------------------------------------------------------------
__global__ __launch_bounds__(256, 1)
void tc_gemm_scores(const __nv_bfloat16* __restrict__ Ahi, const __nv_bfloat16* __restrict__ Alo,
                    const __nv_bfloat16* __restrict__ Bhi, const __nv_bfloat16* __restrict__ Blo,
                    const float* __restrict__ dec, const float* __restrict__ cov,
                    const float* __restrict__ vvec, float* __restrict__ scores_part,
                    int M, int N, int K, int T)
{
    GEMM_PREAMBLE();
    GEMM_MAINLOOP();

    __syncthreads();                    // smem stages now reusable as scratch
    float* red = (float*)smem;          // [128][4]

#pragma unroll
    for (int mt = 0; mt < 4; mt++) {
        const int rl0 = wm * 64 + mt * 16 + (lane >> 2);
        const int rl1 = rl0 + 8;
        const int gr0 = brow + rl0, gr1 = brow + rl1;
        const float cov0 = cov[gr0], cov1 = cov[gr1];
        const float* dec0 = dec + (size_t)(gr0 / T) * 1024;
        const float* dec1 = dec + (size_t)(gr1 / T) * 1024;
        float s0 = 0.0f, s1 = 0.0f;
#pragma unroll
        for (int nt = 0; nt < 4; nt++) {
            const int c0 = bcol + wn * 32 + nt * 8 + (lane & 3) * 2;
            const float va = vvec[c0], vb = vvec[c0 + 1];
            const float da = dec0[c0], db = dec0[c0 + 1];
            const float ea = dec1[c0], eb = dec1[c0 + 1];
            s0 += tanh_fma(acc[mt][nt][0] + da + cov0) * va
                + tanh_fma(acc[mt][nt][1] + db + cov0) * vb;
            s1 += tanh_fma(acc[mt][nt][2] + ea + cov1) * va
                + tanh_fma(acc[mt][nt][3] + eb + cov1) * vb;
        }
        s0 += __shfl_xor_sync(0xffffffffu, s0, 1);
        s0 += __shfl_xor_sync(0xffffffffu, s0, 2);
        s1 += __shfl_xor_sync(0xffffffffu, s1, 1);
        s1 += __shfl_xor_sync(0xffffffffu, s1, 2);
        if ((lane & 3) == 0) {
            red[rl0 * 4 + wn] = s0;
            red[rl1 * 4 + wn] = s1;
        }
    }
    __syncthreads();
    if (tid < 128) {
        float t = red[tid * 4] + red[tid * 4 + 1] + red[tid * 4 + 2] + red[tid * 4 + 3];
        scores_part[(size_t)(brow + tid) * 8 + blockIdx.x] = t;
    }
}

// ---------------------------------------------------------------------------
// conversion kernels
// ---------------------------------------------------------------------------
// 4 independent float4 loads per thread (MLP=4). Requires n4 % 1024 == 0.
__global__ void split_f32(const float* __restrict__ in, __nv_bfloat16* __restrict__ hi,
                          __nv_bfloat16* __restrict__ lo, int n4)
{
    const int base = blockIdx.x * 1024 + threadIdx.x;
    float4 v[4];
#pragma unroll
    for (int j = 0; j < 4; j++) v[j] = ((const float4*)in)[base + j * 256];
#pragma unroll
    for (int j = 0; j < 4; j++) {
        const int i = base + j * 256;
        __nv_bfloat16 h0 = __float2bfloat16(v[j].x), h1 = __float2bfloat16(v[j].y);
        __nv_bfloat16 h2 = __float2bfloat16(v[j].z), h3 = __float2bfloat16(v[j].w);
        ((uint2*)hi)[i] = make_uint2(pack_bf2(__bfloat162float(h0), __bfloat162float(h1)),
                                     pack_bf2(__bfloat162float(h2), __bfloat162float(h3)));
        ((uint2*)lo)[i] = make_uint2(pack_bf2(v[j].x - __bfloat162float(h0), v[j].y - __bfloat162float(h1)),
                                     pack_bf2(v[j].z - __bfloat162float(h2), v[j].w - __bfloat162float(h3)));
    }
}

__global__ void transpose_split(const float* __restrict__ in,
                                __nv_bfloat16* __restrict__ hi,
                                __nv_bfloat16* __restrict__ lo, int K, int N)
{
    __shared__ float t[32][33];
    const int n0 = blockIdx.x * 32, k0 = blockIdx.y * 32;
    const int tx = threadIdx.x, ty = threadIdx.y;
#pragma unroll
    for (int i = 0; i < 32; i += 8)
        t[ty + i][tx] = in[(size_t)(k0 + ty + i) * N + n0 + tx];
    __syncthreads();
#pragma unroll
    for (int i = 0; i < 32; i += 8) {
        float v = t[tx][ty + i];
        __nv_bfloat16 h = __float2bfloat16(v);
        const size_t o = (size_t)(n0 + ty + i) * K + k0 + tx;
        hi[o] = h;
        lo[o] = __float2bfloat16(v - __bfloat162float(h));
    }
}

__global__ void bfused_kernel(const float* __restrict__ bg, const float* __restrict__ Gs,
                              const float* __restrict__ bgs, float* __restrict__ out,
                              int K, int N)
{
    __shared__ float red[8][32];
    const int c  = threadIdx.x & 31;
    const int kg = threadIdx.x >> 5;
    const int n  = blockIdx.x * 32 + c;
    const int kslice = K / 8;
    float acc = 0.0f;
    const float* p = Gs + (size_t)(kg * kslice) * N + n;
#pragma unroll 8
    for (int k = 0; k < kslice; k++)
        acc = fmaf(bg[kg * kslice + k], p[(size_t)k * N], acc);
    red[kg][c] = acc;
    __syncthreads();
    if (kg == 0) {
        float s = bgs[n];
#pragma unroll
        for (int i = 0; i < 8; i++) s += red[i][c];
        out[n] = s;
    }
}

__global__ void dec_proj(const float* __restrict__ sth, const float* __restrict__ W,
                         const float* __restrict__ bias, float* __restrict__ out)
{
    __shared__ float s[1024];
    const int b = blockIdx.y;
    const int col = blockIdx.x * 128 + threadIdx.x;
    for (int k = threadIdx.x; k < 1024; k += 128) s[k] = sth[b * 1024 + k];
    __syncthreads();
    float acc = 0.0f;
#pragma unroll 16
    for (int k = 0; k < 1024; k++) acc = fmaf(s[k], W[(size_t)k * 1024 + col], acc);
    out[b * 1024 + col] = acc + bias[col];
}

// ---------------------------------------------------------------------------
// fused softmax + context: grid (b, DH/256), 256 threads.
// Each block recomputes the tiny softmax from score partials (deterministic,
// identical across blocks), then computes its 256-column context slice.
// Blocks with blockIdx.y == 0 also write coverage/alpha outputs.
// ---------------------------------------------------------------------------
__global__ void softmax_context_kernel(const float* __restrict__ scores_part,
                                       const float* __restrict__ cov,
                                       const float* __restrict__ Gstar,
                                       float* __restrict__ out_c,
                                       float* __restrict__ out_cov,
                                       float* __restrict__ out_alpha,
                                       int T, int DH)
{
    const int b = blockIdx.x;
    const int tid = threadIdx.x;
    __shared__ float sc[256];
    __shared__ float red[256];
    __shared__ float a_s[256];

    float myv = -1e30f;
    if (tid < T) {
        const float4* p = (const float4*)(scores_part + (size_t)(b * T + tid) * 8);
        float4 x = p[0], y = p[1];
        myv = (x.x + x.y + x.z + x.w) + (y.x + y.y + y.z + y.w);
        sc[tid] = myv;
    }
    red[tid] = myv;
    __syncthreads();
    for (int off = 128; off > 0; off >>= 1) {
        if (tid < off) red[tid] = fmaxf(red[tid], red[tid + off]);
        __syncthreads();
    }
    const float m = red[0];
    __syncthreads();
    float e = 0.0f;
    if (tid < T) e = expf(sc[tid] - m);
    red[tid] = e;
    __syncthreads();
    for (int off = 128; off > 0; off >>= 1) {
        if (tid < off) red[tid] += red[tid + off];
        __syncthreads();
    }
    const float inv = 1.0f / red[0];
    const float a = e * inv;
    a_s[tid] = a;
    if (blockIdx.y == 0 && tid < T) {
        out_alpha[b * T + tid] = a;
        out_cov[b * T + tid]   = cov[b * T + tid] + a;
    }
    __syncthreads();

    const int d = blockIdx.y * 256 + tid;
    const float* gbase = Gstar + (size_t)b * T * DH + d;
    float acc = 0.0f;
#pragma unroll 4
    for (int t = 0; t < T; t++)
        acc = fmaf(a_s[t], gbase[(size_t)t * DH], acc);
    out_c[(size_t)b * DH + d] = acc;
}

// ---------------------------------------------------------------------------
extern "C" void kernel_launch(void* const* d_in, const int* in_sizes, int n_in,
                              void* d_out, int out_size)
{
    const float* gf   = (const float*)d_in[0];
    const float* sth  = (const float*)d_in[1];
    const float* cov  = (const float*)d_in[2];
    const float* Wg   = (const float*)d_in[3];
    const float* bg   = (const float*)d_in[4];
    const float* Gs   = (const float*)d_in[5];
    const float* bgs  = (const float*)d_in[6];
    const float* Wgs  = (const float*)d_in[7];
    const float* Wdec = (const float*)d_in[8];
    const float* bdec = (const float*)d_in[9];
    const float* v    = (const float*)d_in[10];

    const int GFD = in_sizes[4];        // 4096
    const int DH  = in_sizes[9];        // 1024
    const int b   = in_sizes[1] / DH;   // 32
    const int T   = in_sizes[2] / b;    // 196
    const int M   = b * T;              // 6272

    __nv_bfloat16 *gf_hi, *gf_lo, *Wg_hi, *Wg_lo, *GsT_hi, *GsT_lo;
    __nv_bfloat16 *WfT_hi, *WfT_lo, *WgsT_hi, *WgsT_lo, *Gstar_hi, *Gstar_lo;
    float *Gstar, *bfused, *dec, *scores_part;
    cudaGetSymbolAddress((void**)&gf_hi, g_gf_hi);
    cudaGetSymbolAddress((void**)&gf_lo, g_gf_lo);
    cudaGetSymbolAddress((void**)&Wg_hi, g_Wg_hi);
    cudaGetSymbolAddress((void**)&Wg_lo, g_Wg_lo);
    cudaGetSymbolAddress((void**)&GsT_hi, g_GsT_hi);
    cudaGetSymbolAddress((void**)&GsT_lo, g_GsT_lo);
    cudaGetSymbolAddress((void**)&WfT_hi, g_WfT_hi);
    cudaGetSymbolAddress((void**)&WfT_lo, g_WfT_lo);
    cudaGetSymbolAddress((void**)&WgsT_hi, g_WgsT_hi);
    cudaGetSymbolAddress((void**)&WgsT_lo, g_WgsT_lo);
    cudaGetSymbolAddress((void**)&Gstar, g_Gstar);
    cudaGetSymbolAddress((void**)&Gstar_hi, g_Gstar_hi);
    cudaGetSymbolAddress((void**)&Gstar_lo, g_Gstar_lo);
    cudaGetSymbolAddress((void**)&bfused, g_bfused);
    cudaGetSymbolAddress((void**)&dec, g_dec);
    cudaGetSymbolAddress((void**)&scores_part, g_scores_part);

    cudaFuncSetAttribute(tc_gemm, cudaFuncAttributeMaxDynamicSharedMemorySize, GEMM_SMEM);
    cudaFuncSetAttribute(tc_gemm_scores, cudaFuncAttributeMaxDynamicSharedMemorySize, GEMM_SMEM);

    // operand prep
    split_f32<<<M * GFD / 4096, 256>>>(gf, gf_hi, gf_lo, M * GFD / 4);
    split_f32<<<GFD * GFD / 4096, 256>>>(Wg, Wg_hi, Wg_lo, GFD * GFD / 4);
    transpose_split<<<dim3(DH / 32, GFD / 32), dim3(32, 8)>>>(Gs, GsT_hi, GsT_lo, GFD, DH);
    transpose_split<<<dim3(DH / 32, DH / 32), dim3(32, 8)>>>(Wgs, WgsT_hi, WgsT_lo, DH, DH);
    bfused_kernel<<<DH / 32, 256>>>(bg, Gs, bgs, bfused, GFD, DH);
    dec_proj<<<dim3(DH / 128, b), 128>>>(sth, Wdec, bdec, dec);

    // WfT[n,m] = sum_k Gs[k,n] * Wg[m,k]
    tc_gemm<<<dim3(GFD / 128, DH / 128), 256, GEMM_SMEM>>>(
        GsT_hi, GsT_lo, Wg_hi, Wg_lo, nullptr, nullptr, WfT_hi, WfT_lo, DH, GFD, GFD);
    // g_star = gf @ Wf + bfused
    tc_gemm<<<dim3(DH / 128, M / 128), 256, GEMM_SMEM>>>(
        gf_hi, gf_lo, WfT_hi, WfT_lo, bfused, Gstar, Gstar_hi, Gstar_lo, M, DH, GFD);
    // wgs = g_star @ Wgs, fused into score partials
    tc_gemm_scores<<<dim3(DH / 128, M / 128), 256, GEMM_SMEM>>>(
        Gstar_hi, Gstar_lo, WgsT_hi, WgsT_lo, dec, cov, v, scores_part, M, DH, DH, T);

    float* out_c     = (float*)d_out;
    float* out_cov   = out_c + (size_t)b * DH;
    float* out_alpha = out_cov + (size_t)b * T;
    softmax_context_kernel<<<dim3(b, DH / 256), 256>>>(
        scores_part, cov, Gstar, out_c, out_cov, out_alpha, T, DH);
}

// round 13
// speedup vs baseline: 1.0736x; 1.0302x over previous
#include <cuda_runtime.h>
#include <cuda_bf16.h>
#include <cstdint>
#include <math.h>

// ---------------------------------------------------------------------------
// img_attention, mma.sync (HMMA) split-bf16 path, fused-weight algebra:
//   WfT    = (Wg @ Gs)^T            [1024, 4096]
//   bfused = bg @ Gs + bgs          [1024]
//   g_star = gf @ Wf + bfused       [M, 1024]
//   wgs    = g_star @ Wgs  (fused into scores partials, never materialized)
//   dec    = s_t_hat @ Wdec + bdec  [32, 1024]
//   scores = tanh(wgs + dec + cov) @ v; alpha = softmax_T; c = alpha @ g_star
// Output: [c_img (b*DH) | coverage_new (b*T) | alpha (b*T)]
// Launch order places GEMM2 at index 3 (the ncu-captured slot).
// ---------------------------------------------------------------------------

#define MME   6272
#define GFDE  4096
#define DHE   1024

// ---- scratch (__device__ globals; allocation-free rule) ----
__device__ __align__(1024) __nv_bfloat16 g_gf_hi[25690112];
__device__ __align__(1024) __nv_bfloat16 g_gf_lo[25690112];
__device__ __align__(1024) __nv_bfloat16 g_Wg_hi[16777216];
__device__ __align__(1024) __nv_bfloat16 g_Wg_lo[16777216];
__device__ __align__(1024) __nv_bfloat16 g_GsT_hi[4194304];
__device__ __align__(1024) __nv_bfloat16 g_GsT_lo[4194304];
__device__ __align__(1024) __nv_bfloat16 g_WfT_hi[4194304];
__device__ __align__(1024) __nv_bfloat16 g_WfT_lo[4194304];
__device__ __align__(1024) __nv_bfloat16 g_WgsT_hi[1048576];
__device__ __align__(1024) __nv_bfloat16 g_WgsT_lo[1048576];
__device__ __align__(1024) float g_Gstar[6422528];
__device__ __align__(1024) __nv_bfloat16 g_Gstar_hi[6422528];
__device__ __align__(1024) __nv_bfloat16 g_Gstar_lo[6422528];
__device__ __align__(1024) float g_bfused[1024];
__device__ __align__(1024) float g_dec[32768];
__device__ __align__(1024) float g_scores_part[50176];   // [M][8]

// ---------------------------------------------------------------------------
// helpers
// ---------------------------------------------------------------------------
__device__ __forceinline__ uint32_t smem_u32(const void* p) {
    uint32_t a;
    asm("{ .reg .u64 t; cvta.to.shared.u64 t, %1; cvt.u32.u64 %0, t; }" : "=r"(a) : "l"(p));
    return a;
}
__device__ __forceinline__ void cp16(uint32_t s, const void* g) {
    asm volatile("cp.async.cg.shared.global [%0], [%1], 16;" :: "r"(s), "l"(g));
}
__device__ __forceinline__ void ldsm4(uint32_t* r, uint32_t a) {
    asm volatile("ldmatrix.sync.aligned.m8n8.x4.shared.b16 {%0,%1,%2,%3}, [%4];"
                 : "=r"(r[0]), "=r"(r[1]), "=r"(r[2]), "=r"(r[3]) : "r"(a));
}
__device__ __forceinline__ void mma16816(float* d, const uint32_t* a, const uint32_t* b) {
    asm volatile(
        "mma.sync.aligned.m16n8k16.row.col.f32.bf16.bf16.f32 "
        "{%0,%1,%2,%3}, {%4,%5,%6,%7}, {%8,%9}, {%0,%1,%2,%3};"
        : "+f"(d[0]), "+f"(d[1]), "+f"(d[2]), "+f"(d[3])
        : "r"(a[0]), "r"(a[1]), "r"(a[2]), "r"(a[3]), "r"(b[0]), "r"(b[1]));
}
__device__ __forceinline__ uint32_t pack_bf2(float x, float y) {
    __nv_bfloat162 h = __floats2bfloat162_rn(x, y);
    return *(uint32_t*)&h;
}

// MUFU-free tanh (FMA poly exp2 + Newton reciprocal), abs err ~3e-6.
__device__ __forceinline__ float tanh_fma(float x) {
    float ax = fminf(fabsf(x), 9.0f);
    float y  = -2.88539008f * ax;
    float nf = rintf(y);
    float f  = y - nf;
    float p  = 1.33335581e-3f;
    p = fmaf(p, f, 9.61812910e-3f);
    p = fmaf(p, f, 5.55041087e-2f);
    p = fmaf(p, f, 2.40226507e-1f);
    p = fmaf(p, f, 6.93147181e-1f);
    p = fmaf(p, f, 1.0f);
    int ni = (int)nf;
    float u = __int_as_float(__float_as_int(p) + (ni << 23));
    float d = 1.0f + u;
    float r = fmaf(-0.5f, d, 1.45711f);
    r = r * fmaf(-d, r, 2.0f);
    r = r * fmaf(-d, r, 2.0f);
    r = r * fmaf(-d, r, 2.0f);
    return copysignf((1.0f - u) * r, x);
}

// ---------------------------------------------------------------------------
// HMMA GEMM (BN=128): C[M,N] = A[M,K] @ B^T, split-bf16 3xMMA.
// BM=128, BN=128, BK=64, 3-stage cp.async, 8 warps (2m x 4n), warp 64x32.
// ---------------------------------------------------------------------------
#define BKT 64
#define OP_BYTES (128 * 64 * 2)          // 16 KB per operand tile
#define STG_BYTES (4 * OP_BYTES)         // 64 KB per stage
#define GEMM_SMEM (3 * STG_BYTES)        // 192 KB

__device__ __forceinline__ void load_stage(uint32_t stg,
    const __nv_bfloat16* __restrict__ Ah, const __nv_bfloat16* __restrict__ Al,
    const __nv_bfloat16* __restrict__ Bh, const __nv_bfloat16* __restrict__ Bl,
    int brow, int bcol, int K, int k0, int tid)
{
#pragma unroll
    for (int op = 0; op < 4; op++) {
        const __nv_bfloat16* P = (op == 0) ? Ah : (op == 1) ? Al : (op == 2) ? Bh : Bl;
        const int row0 = (op < 2) ? brow : bcol;
#pragma unroll
        for (int it = 0; it < 4; it++) {
            int idx = tid + it * 256;
            int r = idx >> 3, c = idx & 7;
            uint32_t dst = stg + op * OP_BYTES + r * 128 + (((uint32_t)(c ^ (r & 7))) << 4);
            cp16(dst, P + (size_t)(row0 + r) * K + k0 + c * 8);
        }
    }
}

#define LOAD_FRAGS(buf, ks)                                                    \
    {                                                                          \
        const uint32_t cA = ((uint32_t)(((ks) * 2 + hiA) ^ phA)) << 4;         \
        const uint32_t cB = ((uint32_t)(((ks) * 2 + hiB) ^ phB)) << 4;         \
        _Pragma("unroll")                                                      \
        for (int mt = 0; mt < 4; mt++) {                                       \
            uint32_t ro = (uint32_t)(rowA + mt * 16) * 128 + cA;               \
            ldsm4(ah[buf][mt], aH + ro);                                       \
            ldsm4(al[buf][mt], aL + ro);                                       \
        }                                                                      \
        _Pragma("unroll")                                                      \
        for (int p = 0; p < 2; p++) {                                          \
            uint32_t ro = (uint32_t)(rowB + p * 16) * 128 + cB;                \
            ldsm4(bh[buf][p], bH + ro);                                        \
            ldsm4(bl[buf][p], bL + ro);                                        \
        }                                                                      \
    }

#define DO_MMAS(buf)                                                           \
    _Pragma("unroll")                                                          \
    for (int mt = 0; mt < 4; mt++)                                             \
        _Pragma("unroll")                                                      \
        for (int nt = 0; nt < 4; nt++) {                                       \
            float* d = acc[mt][nt];                                            \
            const uint32_t* bhf = &bh[buf][nt >> 1][(nt & 1) * 2];             \
            const uint32_t* blf = &bl[buf][nt >> 1][(nt & 1) * 2];             \
            mma16816(d, ah[buf][mt], bhf);                                     \
            mma16816(d, ah[buf][mt], blf);                                     \
            mma16816(d, al[buf][mt], bhf);                                     \
        }

#define GEMM_MAINLOOP()                                                        \
    load_stage(sbase, Ahi, Alo, Bhi, Blo, brow, bcol, K, 0, tid);              \
    asm volatile("cp.async.commit_group;" ::: "memory");                       \
    if (KT > 1) {                                                              \
        load_stage(sbase + STG_BYTES, Ahi, Alo, Bhi, Blo, brow, bcol, K, BKT, tid); \
        asm volatile("cp.async.commit_group;" ::: "memory");                   \
    }                                                                          \
    for (int kt = 0; kt < KT; kt++) {                                          \
        if (kt + 1 < KT) asm volatile("cp.async.wait_group 1;" ::: "memory");  \
        else             asm volatile("cp.async.wait_group 0;" ::: "memory");  \
        __syncthreads();                                                       \
        const uint32_t stg = sbase + (kt % 3) * STG_BYTES;                     \
        const uint32_t aH = stg, aL = stg + OP_BYTES;                          \
        const uint32_t bH = stg + 2 * OP_BYTES, bL = stg + 3 * OP_BYTES;       \
        uint32_t ah[2][4][4], al[2][4][4], bh[2][2][4], bl[2][2][4];           \
        LOAD_FRAGS(0, 0);                                                      \
        _Pragma("unroll")                                                      \
        for (int ks = 0; ks < 4; ks++) {                                       \
            if (ks < 3) { LOAD_FRAGS((ks + 1) & 1, ks + 1); }                  \
            DO_MMAS(ks & 1);                                                   \
        }                                                                      \
        if (kt + 2 < KT) {                                                     \
            load_stage(sbase + ((kt + 2) % 3) * STG_BYTES,                     \
                       Ahi, Alo, Bhi, Blo, brow, bcol, K, (kt + 2) * BKT, tid);\
            asm volatile("cp.async.commit_group;" ::: "memory");               \
        }                                                                      \
    }

#define GEMM_PREAMBLE()                                                        \
    extern __shared__ __align__(128) char smem[];                              \
    const uint32_t sbase = smem_u32(smem);                                     \
    const int tid = threadIdx.x, wid = tid >> 5, lane = tid & 31;              \
    const int wm = wid >> 2, wn = wid & 3;                                     \
    const int brow = blockIdx.y * 128, bcol = blockIdx.x * 128;                \
    const int KT = K / BKT;                                                    \
    const int rowA = wm * 64 + (lane & 15);                                    \
    const int phA  = rowA & 7;                                                 \
    const int hiA  = lane >> 4;                                                \
    const int rowB = wn * 32 + ((lane >> 4) << 3) + (lane & 7);                \
    const int phB  = lane & 7;                                                 \
    const int hiB  = (lane >> 3) & 1;                                          \
    float acc[4][4][4];                                                        \
    _Pragma("unroll")                                                          \
    for (int mt = 0; mt < 4; mt++)                                             \
        _Pragma("unroll")                                                      \
        for (int nt = 0; nt < 4; nt++)                                         \
            _Pragma("unroll")                                                  \
            for (int j = 0; j < 4; j++) acc[mt][nt][j] = 0.0f;

__global__ __launch_bounds__(256, 1)
void tc_gemm(const __nv_bfloat16* __restrict__ Ahi, const __nv_bfloat16* __restrict__ Alo,
             const __nv_bfloat16* __restrict__ Bhi, const __nv_bfloat16* __restrict__ Blo,
             const float* __restrict__ bias,
             float* __restrict__ Cf, __nv_bfloat16* __restrict__ Chi,
             __nv_bfloat16* __restrict__ Clo,
             int M, int N, int K)
{
    GEMM_PREAMBLE();
    GEMM_MAINLOOP();

#pragma unroll
    for (int mt = 0; mt < 4; mt++)
#pragma unroll
        for (int nt = 0; nt < 4; nt++) {
            const int r0 = brow + wm * 64 + mt * 16 + (lane >> 2);
            const int c0 = bcol + wn * 32 + nt * 8 + (lane & 3) * 2;
            float v0 = acc[mt][nt][0], v1 = acc[mt][nt][1];
            float v2 = acc[mt][nt][2], v3 = acc[mt][nt][3];
            if (bias) {
                float b0 = bias[c0], b1 = bias[c0 + 1];
                v0 += b0; v1 += b1; v2 += b0; v3 += b1;
            }
            const size_t o0 = (size_t)r0 * N + c0;
            const size_t o1 = (size_t)(r0 + 8) * N + c0;
            if (Cf) {
                *(float2*)&Cf[o0] = make_float2(v0, v1);
                *(float2*)&Cf[o1] = make_float2(v2, v3);
            }
            if (Chi) {
                __nv_bfloat16 h0 = __float2bfloat16(v0), h1 = __float2bfloat16(v1);
                __nv_bfloat16 h2 = __float2bfloat16(v2), h3 = __float2bfloat16(v3);
                *(uint32_t*)&Chi[o0] = pack_bf2(__bfloat162float(h0), __bfloat162float(h1));
                *(uint32_t*)&Chi[o1] = pack_bf2(__bfloat162float(h2), __bfloat162float(h3));
                *(uint32_t*)&Clo[o0] = pack_bf2(v0 - __bfloat162float(h0), v1 - __bfloat162float(h1));
                *(uint32_t*)&Clo[o1] = pack_bf2(v2 - __bfloat162float(h2), v3 - __bfloat162float(h3));
            }
        }
}

// ---------------------------------------------------------------------------
// GEMM3 fused: wgs tile -> tanh(wgs + dec + cov) * v -> scores_part.
// ---------------------------------------------------------------------------
__global__ __launch_bounds__(256, 1)
void tc_gemm_scores(const __nv_bfloat16* __restrict__ Ahi, const __nv_bfloat16* __restrict__ Alo,
                    const __nv_bfloat16* __restrict__ Bhi, const __nv_bfloat16* __restrict__ Blo,
                    const float* __restrict__ dec, const float* __restrict__ cov,
                    const float* __restrict__ vvec, float* __restrict__ scores_part,
                    int M, int N, int K, int T)
{
    GEMM_PREAMBLE();
    GEMM_MAINLOOP();

    __syncthreads();
    float* red = (float*)smem;          // [128][4]

#pragma unroll
    for (int mt = 0; mt < 4; mt++) {
        const int rl0 = wm * 64 + mt * 16 + (lane >> 2);
        const int rl1 = rl0 + 8;
        const int gr0 = brow + rl0, gr1 = brow + rl1;
        const float cov0 = cov[gr0], cov1 = cov[gr1];
        const float* dec0 = dec + (size_t)(gr0 / T) * 1024;
        const float* dec1 = dec + (size_t)(gr1 / T) * 1024;
        float s0 = 0.0f, s1 = 0.0f;
#pragma unroll
        for (int nt = 0; nt < 4; nt++) {
            const int c0 = bcol + wn * 32 + nt * 8 + (lane & 3) * 2;
            const float va = vvec[c0], vb = vvec[c0 + 1];
            const float da = dec0[c0], db = dec0[c0 + 1];
            const float ea = dec1[c0], eb = dec1[c0 + 1];
            s0 += tanh_fma(acc[mt][nt][0] + da + cov0) * va
                + tanh_fma(acc[mt][nt][1] + db + cov0) * vb;
            s1 += tanh_fma(acc[mt][nt][2] + ea + cov1) * va
                + tanh_fma(acc[mt][nt][3] + eb + cov1) * vb;
        }
        s0 += __shfl_xor_sync(0xffffffffu, s0, 1);
        s0 += __shfl_xor_sync(0xffffffffu, s0, 2);
        s1 += __shfl_xor_sync(0xffffffffu, s1, 1);
        s1 += __shfl_xor_sync(0xffffffffu, s1, 2);
        if ((lane & 3) == 0) {
            red[rl0 * 4 + wn] = s0;
            red[rl1 * 4 + wn] = s1;
        }
    }
    __syncthreads();
    if (tid < 128) {
        float t = red[tid * 4] + red[tid * 4 + 1] + red[tid * 4 + 2] + red[tid * 4 + 3];
        scores_part[(size_t)(brow + tid) * 8 + blockIdx.x] = t;
    }
}

// ---------------------------------------------------------------------------
// prep_all: block-range dispatch of all independent prep work.
//   [0, NB_GF)          split gf          (1024 float4 per block, MLP=4)
//   [.., +NB_WG)        split Wg
//   [.., +NB_TGS)       transpose+split Gs   [GFD,DH] -> [DH,GFD]
//   [.., +NB_TWGS)      transpose+split Wgs  [DH,DH]  -> [DH,DH]
//   [.., +NB_BF)        bfused
// all with 256 threads.
// ---------------------------------------------------------------------------
#define NB_GF   (MME * GFDE / 4096)          // 6272
#define NB_WG   (GFDE * GFDE / 4096)         // 4096
#define NB_TGS  ((DHE / 32) * (GFDE / 32))   // 4096
#define NB_TWGS ((DHE / 32) * (DHE / 32))    // 1024
#define NB_BF   (DHE / 32)                   // 32

__device__ __forceinline__ void split_blk(const float* __restrict__ in,
                                          __nv_bfloat16* __restrict__ hi,
                                          __nv_bfloat16* __restrict__ lo,
                                          int blk, int tid)
{
    const int base = blk * 1024 + tid;
    float4 v[4];
#pragma unroll
    for (int j = 0; j < 4; j++) v[j] = ((const float4*)in)[base + j * 256];
#pragma unroll
    for (int j = 0; j < 4; j++) {
        const int i = base + j * 256;
        __nv_bfloat16 h0 = __float2bfloat16(v[j].x), h1 = __float2bfloat16(v[j].y);
        __nv_bfloat16 h2 = __float2bfloat16(v[j].z), h3 = __float2bfloat16(v[j].w);
        ((uint2*)hi)[i] = make_uint2(pack_bf2(__bfloat162float(h0), __bfloat162float(h1)),
                                     pack_bf2(__bfloat162float(h2), __bfloat162float(h3)));
        ((uint2*)lo)[i] = make_uint2(pack_bf2(v[j].x - __bfloat162float(h0), v[j].y - __bfloat162float(h1)),
                                     pack_bf2(v[j].z - __bfloat162float(h2), v[j].w - __bfloat162float(h3)));
    }
}

__device__ __forceinline__ void transp_blk(const float* __restrict__ in,
                                           __nv_bfloat16* __restrict__ hi,
                                           __nv_bfloat16* __restrict__ lo,
                                           int K, int N, int bx, int by,
                                           int tid, float* t /* [32][33] smem */)
{
    const int n0 = bx * 32, k0 = by * 32;
    const int tx = tid & 31, ty = tid >> 5;
#pragma unroll
    for (int i = 0; i < 32; i += 8)
        t[(ty + i) * 33 + tx] = in[(size_t)(k0 + ty + i) * N + n0 + tx];
    __syncthreads();
#pragma unroll
    for (int i = 0; i < 32; i += 8) {
        float v = t[tx * 33 + ty + i];
        __nv_bfloat16 h = __float2bfloat16(v);
        const size_t o = (size_t)(n0 + ty + i) * K + k0 + tx;
        hi[o] = h;
        lo[o] = __float2bfloat16(v - __bfloat162float(h));
    }
}

__global__ __launch_bounds__(256)
void prep_all(const float* __restrict__ gf, const float* __restrict__ Wg,
              const float* __restrict__ Gs, const float* __restrict__ Wgs,
              const float* __restrict__ bg, const float* __restrict__ bgs,
              __nv_bfloat16* __restrict__ gf_hi, __nv_bfloat16* __restrict__ gf_lo,
              __nv_bfloat16* __restrict__ Wg_hi, __nv_bfloat16* __restrict__ Wg_lo,
              __nv_bfloat16* __restrict__ GsT_hi, __nv_bfloat16* __restrict__ GsT_lo,
              __nv_bfloat16* __restrict__ WgsT_hi, __nv_bfloat16* __restrict__ WgsT_lo,
              float* __restrict__ bfused)
{
    __shared__ float t[32 * 33];
    const int tid = threadIdx.x;
    int blk = blockIdx.x;

    if (blk < NB_GF) { split_blk(gf, gf_hi, gf_lo, blk, tid); return; }
    blk -= NB_GF;
    if (blk < NB_WG) { split_blk(Wg, Wg_hi, Wg_lo, blk, tid); return; }
    blk -= NB_WG;
    if (blk < NB_TGS) {
        transp_blk(Gs, GsT_hi, GsT_lo, GFDE, DHE, blk & 31, blk >> 5, tid, t);
        return;
    }
    blk -= NB_TGS;
    if (blk < NB_TWGS) {
        transp_blk(Wgs, WgsT_hi, WgsT_lo, DHE, DHE, blk & 31, blk >> 5, tid, t);
        return;
    }
    blk -= NB_TWGS;
    {   // bfused: 32 blocks, 256 threads = 32 cols x 8 k-groups
        __shared__ float red[8][32];
        const int c  = tid & 31;
        const int kg = tid >> 5;
        const int n  = blk * 32 + c;
        const int kslice = GFDE / 8;
        float acc = 0.0f;
        const float* p = Gs + (size_t)(kg * kslice) * DHE + n;
#pragma unroll 8
        for (int k = 0; k < kslice; k++)
            acc = fmaf(bg[kg * kslice + k], p[(size_t)k * DHE], acc);
        red[kg][c] = acc;
        __syncthreads();
        if (kg == 0) {
            float s = bgs[n];
#pragma unroll
            for (int i = 0; i < 8; i++) s += red[i][c];
            bfused[n] = s;
        }
    }
}

// dec[b, col] = s_t_hat[b,:] @ Wdec[:, col] + bdec[col]; 256 threads, 256 cols
__global__ void dec_proj(const float* __restrict__ sth, const float* __restrict__ W,
                         const float* __restrict__ bias, float* __restrict__ out)
{
    __shared__ float s[1024];
    const int b = blockIdx.y;
    const int col = blockIdx.x * 256 + threadIdx.x;
    for (int k = threadIdx.x; k < 1024; k += 256) s[k] = sth[b * 1024 + k];
    __syncthreads();
    float acc = 0.0f;
#pragma unroll 16
    for (int k = 0; k < 1024; k++) acc = fmaf(s[k], W[(size_t)k * 1024 + col], acc);
    out[b * 1024 + col] = acc + bias[col];
}

// ---------------------------------------------------------------------------
// fused softmax + context: grid (b, DH/256), 256 threads.
// ---------------------------------------------------------------------------
__global__ void softmax_context_kernel(const float* __restrict__ scores_part,
                                       const float* __restrict__ cov,
                                       const float* __restrict__ Gstar,
                                       float* __restrict__ out_c,
                                       float* __restrict__ out_cov,
                                       float* __restrict__ out_alpha,
                                       int T, int DH)
{
    const int b = blockIdx.x;
    const int tid = threadIdx.x;
    __shared__ float sc[256];
    __shared__ float red[256];
    __shared__ float a_s[256];

    float myv = -1e30f;
    if (tid < T) {
        const float4* p = (const float4*)(scores_part + (size_t)(b * T + tid) * 8);
        float4 x = p[0], y = p[1];
        myv = (x.x + x.y + x.z + x.w) + (y.x + y.y + y.z + y.w);
        sc[tid] = myv;
    }
    red[tid] = myv;
    __syncthreads();
    for (int off = 128; off > 0; off >>= 1) {
        if (tid < off) red[tid] = fmaxf(red[tid], red[tid + off]);
        __syncthreads();
    }
    const float m = red[0];
    __syncthreads();
    float e = 0.0f;
    if (tid < T) e = expf(sc[tid] - m);
    red[tid] = e;
    __syncthreads();
    for (int off = 128; off > 0; off >>= 1) {
        if (tid < off) red[tid] += red[tid + off];
        __syncthreads();
    }
    const float inv = 1.0f / red[0];
    const float a = e * inv;
    a_s[tid] = a;
    if (blockIdx.y == 0 && tid < T) {
        out_alpha[b * T + tid] = a;
        out_cov[b * T + tid]   = cov[b * T + tid] + a;
    }
    __syncthreads();

    const int d = blockIdx.y * 256 + tid;
    const float* gbase = Gstar + (size_t)b * T * DH + d;
    float acc = 0.0f;
#pragma unroll 4
    for (int t = 0; t < T; t++)
        acc = fmaf(a_s[t], gbase[(size_t)t * DH], acc);
    out_c[(size_t)b * DH + d] = acc;
}

// ---------------------------------------------------------------------------
extern "C" void kernel_launch(void* const* d_in, const int* in_sizes, int n_in,
                              void* d_out, int out_size)
{
    const float* gf   = (const float*)d_in[0];
    const float* sth  = (const float*)d_in[1];
    const float* cov  = (const float*)d_in[2];
    const float* Wg   = (const float*)d_in[3];
    const float* bg   = (const float*)d_in[4];
    const float* Gs   = (const float*)d_in[5];
    const float* bgs  = (const float*)d_in[6];
    const float* Wgs  = (const float*)d_in[7];
    const float* Wdec = (const float*)d_in[8];
    const float* bdec = (const float*)d_in[9];
    const float* v    = (const float*)d_in[10];

    const int GFD = in_sizes[4];        // 4096
    const int DH  = in_sizes[9];        // 1024
    const int b   = in_sizes[1] / DH;   // 32
    const int T   = in_sizes[2] / b;    // 196
    const int M   = b * T;              // 6272

    __nv_bfloat16 *gf_hi, *gf_lo, *Wg_hi, *Wg_lo, *GsT_hi, *GsT_lo;
    __nv_bfloat16 *WfT_hi, *WfT_lo, *WgsT_hi, *WgsT_lo, *Gstar_hi, *Gstar_lo;
    float *Gstar, *bfused, *dec, *scores_part;
    cudaGetSymbolAddress((void**)&gf_hi, g_gf_hi);
    cudaGetSymbolAddress((void**)&gf_lo, g_gf_lo);
    cudaGetSymbolAddress((void**)&Wg_hi, g_Wg_hi);
    cudaGetSymbolAddress((void**)&Wg_lo, g_Wg_lo);
    cudaGetSymbolAddress((void**)&GsT_hi, g_GsT_hi);
    cudaGetSymbolAddress((void**)&GsT_lo, g_GsT_lo);
    cudaGetSymbolAddress((void**)&WfT_hi, g_WfT_hi);
    cudaGetSymbolAddress((void**)&WfT_lo, g_WfT_lo);
    cudaGetSymbolAddress((void**)&WgsT_hi, g_WgsT_hi);
    cudaGetSymbolAddress((void**)&WgsT_lo, g_WgsT_lo);
    cudaGetSymbolAddress((void**)&Gstar, g_Gstar);
    cudaGetSymbolAddress((void**)&Gstar_hi, g_Gstar_hi);
    cudaGetSymbolAddress((void**)&Gstar_lo, g_Gstar_lo);
    cudaGetSymbolAddress((void**)&bfused, g_bfused);
    cudaGetSymbolAddress((void**)&dec, g_dec);
    cudaGetSymbolAddress((void**)&scores_part, g_scores_part);

    cudaFuncSetAttribute(tc_gemm, cudaFuncAttributeMaxDynamicSharedMemorySize, GEMM_SMEM);
    cudaFuncSetAttribute(tc_gemm_scores, cudaFuncAttributeMaxDynamicSharedMemorySize, GEMM_SMEM);

    // launch 0: all independent prep in one kernel
    const int nb = NB_GF + NB_WG + NB_TGS + NB_TWGS + NB_BF;
    prep_all<<<nb, 256>>>(gf, Wg, Gs, Wgs, bg, bgs,
                          gf_hi, gf_lo, Wg_hi, Wg_lo,
                          GsT_hi, GsT_lo, WgsT_hi, WgsT_lo, bfused);
    // launch 1: GEMM1  WfT[n,m] = sum_k Gs[k,n] * Wg[m,k]
    tc_gemm<<<dim3(GFD / 128, DH / 128), 256, GEMM_SMEM>>>(
        GsT_hi, GsT_lo, Wg_hi, Wg_lo, nullptr, nullptr, WfT_hi, WfT_lo, DH, GFD, GFD);
    // launch 2: dec (needed only by gemm3)
    dec_proj<<<dim3(DH / 256, b), 256>>>(sth, Wdec, bdec, dec);
    // launch 3 (ncu-captured slot): GEMM2  g_star = gf @ Wf + bfused
    tc_gemm<<<dim3(DH / 128, M / 128), 256, GEMM_SMEM>>>(
        gf_hi, gf_lo, WfT_hi, WfT_lo, bfused, Gstar, Gstar_hi, Gstar_lo, M, DH, GFD);
    // launch 4: GEMM3 fused scores
    tc_gemm_scores<<<dim3(DH / 128, M / 128), 256, GEMM_SMEM>>>(
        Gstar_hi, Gstar_lo, WgsT_hi, WgsT_lo, dec, cov, v, scores_part, M, DH, DH, T);

    float* out_c     = (float*)d_out;
    float* out_cov   = out_c + (size_t)b * DH;
    float* out_alpha = out_cov + (size_t)b * T;
    // launch 5: softmax + context + outputs
    softmax_context_kernel<<<dim3(b, DH / 256), 256>>>(
        scores_part, cov, Gstar, out_c, out_cov, out_alpha, T, DH);
}